// round 1
// baseline (speedup 1.0000x reference)
#include <cuda_runtime.h>
#include <math.h>

#define N_NODES 50000
#define F_IN    18
#define NHEADS  8
#define CDIM    64
#define HCDIM   512
#define NE      400000
#define E_TOT   (NE + N_NODES)
#define OUT_DIM 15
#define NEG_SLOPE 0.2f

// ---------------- scratch (static device globals; no runtime allocation) ----------------
__device__ float g_h [N_NODES * HCDIM];   // post-GEMM features of current layer
__device__ float g_x [N_NODES * HCDIM];   // layer activations (ping)
__device__ float g_x3[N_NODES * CDIM];    // layer-3 output (mean over heads)
__device__ float g_as[N_NODES * NHEADS];
__device__ float g_ad[N_NODES * NHEADS];
__device__ float g_alpha[(size_t)E_TOT * NHEADS];   // CSR-ordered attention weights
__device__ int   g_src_sorted[E_TOT];
__device__ int   g_rowptr[N_NODES + 1];
__device__ int   g_cursor[N_NODES];
__device__ int   g_counts[N_NODES];
__device__ int   g_part[64];
__device__ int   g_is64;

// ---------------- edge dtype handling ----------------
// edge_index is declared int64 in the reference, but default JAX demotes to int32.
// Detect at runtime: for int64 (values < 50000, nonnegative) every odd 32-bit word is 0.
__device__ __forceinline__ int edge_at(const int* p, int idx) {
    return g_is64 ? p[2 * idx] : p[idx];
}

__global__ void detect_kernel(const int* __restrict__ p) {
    __shared__ int red[256];
    int acc = 0;
    for (int i = threadIdx.x; i < 8192; i += 256) acc |= p[2 * i + 1];
    red[threadIdx.x] = acc;
    __syncthreads();
    for (int s = 128; s > 0; s >>= 1) {
        if (threadIdx.x < s) red[threadIdx.x] |= red[threadIdx.x + s];
        __syncthreads();
    }
    if (threadIdx.x == 0) g_is64 = (red[0] == 0) ? 1 : 0;
}

// ---------------- CSR build (counting sort by dst; self-loops appended) ----------------
__global__ void init_counts_kernel() {
    int i = blockIdx.x * blockDim.x + threadIdx.x;
    if (i < N_NODES) g_counts[i] = 1;   // self-loop pre-counted
}

__global__ void count_kernel(const int* __restrict__ ei) {
    int i = blockIdx.x * blockDim.x + threadIdx.x;
    if (i < NE) {
        int dst = edge_at(ei, NE + i);
        atomicAdd(&g_counts[dst], 1);
    }
}

__global__ void __launch_bounds__(1024) scan_block_kernel() {
    __shared__ int sm[1024];
    int i = blockIdx.x * 1024 + threadIdx.x;
    int v = (i < N_NODES) ? g_counts[i] : 0;
    sm[threadIdx.x] = v;
    __syncthreads();
    for (int off = 1; off < 1024; off <<= 1) {
        int t = (threadIdx.x >= off) ? sm[threadIdx.x - off] : 0;
        __syncthreads();
        sm[threadIdx.x] += t;
        __syncthreads();
    }
    if (i < N_NODES) g_rowptr[i] = sm[threadIdx.x] - v;   // local exclusive
    if (threadIdx.x == 1023) g_part[blockIdx.x] = sm[1023];
}

__global__ void scan_mid_kernel(int nblocks) {
    if (threadIdx.x == 0) {
        int run = 0;
        for (int b = 0; b < nblocks; b++) { int t = g_part[b]; g_part[b] = run; run += t; }
    }
}

__global__ void __launch_bounds__(1024) scan_add_kernel() {
    int i = blockIdx.x * 1024 + threadIdx.x;
    if (i < N_NODES) {
        int v = g_rowptr[i] + g_part[blockIdx.x];
        g_rowptr[i] = v;
        g_cursor[i] = v;
    }
    if (i == 0) g_rowptr[N_NODES] = E_TOT;
}

__global__ void fill_kernel(const int* __restrict__ ei) {
    int i = blockIdx.x * blockDim.x + threadIdx.x;
    if (i >= E_TOT) return;
    int src, dst;
    if (i < NE) { src = edge_at(ei, i); dst = edge_at(ei, NE + i); }
    else        { src = dst = i - NE; }
    int pos = atomicAdd(&g_cursor[dst], 1);
    g_src_sorted[pos] = src;
}

// ---------------- fp32 tiled GEMM: C[M,Nc] = A[M,K] @ B[K,Nc] ----------------
#define BM 128
#define BN 64
#define BK 16

__global__ void __launch_bounds__(256) gemm_kernel(const float* __restrict__ A,
                                                   const float* __restrict__ B,
                                                   float* __restrict__ C,
                                                   int M, int K, int Nc) {
    __shared__ float As[BK][BM + 4];
    __shared__ float Bs[BK][BN + 4];
    int tid = threadIdx.x;
    int bn0 = blockIdx.x * BN;
    int bm0 = blockIdx.y * BM;
    int tr = tid >> 4;        // 0..15 -> 8 rows each
    int tc = tid & 15;        // 0..15 -> 4 cols each
    int a_row = tid >> 1;           // 0..127
    int a_cb  = (tid & 1) * 8;      // 0 or 8
    int b_row = tid >> 4;           // 0..15
    int b_col = (tid & 15) * 4;

    float acc[8][4];
#pragma unroll
    for (int i = 0; i < 8; i++)
#pragma unroll
        for (int j = 0; j < 4; j++) acc[i][j] = 0.f;

    for (int k0 = 0; k0 < K; k0 += BK) {
        int gm = bm0 + a_row;
#pragma unroll
        for (int i = 0; i < 8; i++) {
            int gk = k0 + a_cb + i;
            As[a_cb + i][a_row] = (gm < M && gk < K) ? A[(long long)gm * K + gk] : 0.f;
        }
        {
            int gk = k0 + b_row;
            float4 bv = make_float4(0.f, 0.f, 0.f, 0.f);
            if (gk < K) bv = *(const float4*)&B[(long long)gk * Nc + bn0 + b_col];
            *(float4*)&Bs[b_row][b_col] = bv;
        }
        __syncthreads();
#pragma unroll
        for (int kk = 0; kk < BK; kk++) {
            float a[8], b[4];
#pragma unroll
            for (int i = 0; i < 8; i++) a[i] = As[kk][tr * 8 + i];
#pragma unroll
            for (int j = 0; j < 4; j++) b[j] = Bs[kk][tc * 4 + j];
#pragma unroll
            for (int i = 0; i < 8; i++)
#pragma unroll
                for (int j = 0; j < 4; j++) acc[i][j] += a[i] * b[j];
        }
        __syncthreads();
    }
#pragma unroll
    for (int i = 0; i < 8; i++) {
        int gm = bm0 + tr * 8 + i;
        if (gm < M) {
#pragma unroll
            for (int j = 0; j < 4; j++)
                C[(long long)gm * Nc + bn0 + tc * 4 + j] = acc[i][j];
        }
    }
}

// ---------------- alpha_s / alpha_d: [N, H] dots against a_src/a_dst ----------------
// warp per (node, head): lane covers channels (lane, lane+32)
__global__ void alpha_kernel(const float* __restrict__ h,
                             const float* __restrict__ a_src,
                             const float* __restrict__ a_dst) {
    int wid = (blockIdx.x * blockDim.x + threadIdx.x) >> 5;
    int lane = threadIdx.x & 31;
    if (wid >= N_NODES * NHEADS) return;
    int n = wid >> 3, hh = wid & 7;
    const float* hp = h + (long long)n * HCDIM + hh * CDIM;
    float v1 = hp[lane], v2 = hp[lane + 32];
    float s1 = a_src[hh * CDIM + lane], s2 = a_src[hh * CDIM + lane + 32];
    float d1 = a_dst[hh * CDIM + lane], d2 = a_dst[hh * CDIM + lane + 32];
    float as = v1 * s1 + v2 * s2;
    float ad = v1 * d1 + v2 * d2;
#pragma unroll
    for (int off = 16; off > 0; off >>= 1) {
        as += __shfl_xor_sync(0xffffffffu, as, off);
        ad += __shfl_xor_sync(0xffffffffu, ad, off);
    }
    if (lane == 0) {
        g_as[n * NHEADS + hh] = as;
        g_ad[n * NHEADS + hh] = ad;
    }
}

// ---------------- segment softmax: streaming max/sum per dst, write per-edge alpha ----------------
// warp handles 4 dst nodes; lane = 8*sub + head
__global__ void stats_kernel() {
    int lane = threadIdx.x & 31;
    int warp = (blockIdx.x * blockDim.x + threadIdx.x) >> 5;
    int sub = lane >> 3, hh = lane & 7;
    int n = warp * 4 + sub;
    if (n >= N_NODES) return;
    int row = g_rowptr[n], end = g_rowptr[n + 1];
    float ad = g_ad[n * NHEADS + hh];
    float m = -INFINITY, s = 0.f;
    for (int j = row; j < end; j++) {
        int src = g_src_sorted[j];
        float e = g_as[src * NHEADS + hh] + ad;
        e = (e > 0.f) ? e : NEG_SLOPE * e;
        float nm = fmaxf(m, e);
        s = s * __expf(m - nm) + __expf(e - nm);
        m = nm;
    }
    float inv = 1.0f / (s + 1e-16f);
    for (int j = row; j < end; j++) {
        int src = g_src_sorted[j];
        float e = g_as[src * NHEADS + hh] + ad;
        e = (e > 0.f) ? e : NEG_SLOPE * e;
        g_alpha[(size_t)j * NHEADS + hh] = __expf(e - m) * inv;
    }
}

// ---------------- heavy aggregation: out[dst] = sum_j alpha_j * h[src_j] ----------------
// block of 512 threads per dst node; one channel per thread. mode 0: +bias, ELU, concat.
// mode 1: mean over heads + bias (layer 3, writes [N, 64]).
__global__ void __launch_bounds__(512) aggregate_kernel(const float* __restrict__ hin,
                                                        const float* __restrict__ bias,
                                                        float* __restrict__ outp,
                                                        int mode) {
    __shared__ float sm[HCDIM];
    int n = blockIdx.x;
    int tid = threadIdx.x;
    int head = tid >> 6;
    int row = g_rowptr[n], end = g_rowptr[n + 1];
    float acc = 0.f;
    for (int j = row; j < end; j++) {
        int src = __ldg(&g_src_sorted[j]);
        float a = __ldg(&g_alpha[(size_t)j * NHEADS + head]);
        acc += a * __ldg(&hin[(long long)src * HCDIM + tid]);
    }
    if (mode == 0) {
        float v = acc + bias[tid];
        outp[(long long)n * HCDIM + tid] = (v > 0.f) ? v : expm1f(v);
    } else {
        sm[tid] = acc;
        __syncthreads();
        if (tid < CDIM) {
            float s = 0.f;
#pragma unroll
            for (int hh = 0; hh < NHEADS; hh++) s += sm[hh * CDIM + tid];
            outp[(long long)n * CDIM + tid] = s * (1.0f / NHEADS) + bias[tid];
        }
    }
}

// ---------------- final projection: out = x3 @ W_out + b_out ----------------
__global__ void __launch_bounds__(256) proj_kernel(const float* __restrict__ x3,
                                                   const float* __restrict__ Wout,
                                                   const float* __restrict__ bout,
                                                   float* __restrict__ out) {
    __shared__ float Ws[CDIM * 16];
    __shared__ float bs[16];
    int tid = threadIdx.x;
    for (int idx = tid; idx < CDIM * 16; idx += 256) {
        int c = idx >> 4, o = idx & 15;
        Ws[idx] = (o < OUT_DIM) ? Wout[c * OUT_DIM + o] : 0.f;
    }
    if (tid < 16) bs[tid] = (tid < OUT_DIM) ? bout[tid] : 0.f;
    __syncthreads();
    int tx = tid & 15;       // out column
    int tn = tid >> 4;       // node within block (16 nodes/block)
    int n = blockIdx.x * 16 + tn;
    if (n >= N_NODES) return;
    const float* xr = x3 + (long long)n * CDIM;
    float acc = 0.f;
#pragma unroll
    for (int c = 0; c < CDIM; c++) acc += xr[c] * Ws[c * 16 + tx];
    if (tx < OUT_DIM) out[(long long)n * OUT_DIM + tx] = acc + bs[tx];
}

// ---------------- launch ----------------
extern "C" void kernel_launch(void* const* d_in, const int* in_sizes, int n_in,
                              void* d_out, int out_size) {
    const float* x    = (const float*)d_in[0];
    const int*   ei   = (const int*)d_in[1];
    const float* W1   = (const float*)d_in[2];
    const float* a1s  = (const float*)d_in[3];
    const float* a1d  = (const float*)d_in[4];
    const float* b1   = (const float*)d_in[5];
    const float* W2   = (const float*)d_in[6];
    const float* a2s  = (const float*)d_in[7];
    const float* a2d  = (const float*)d_in[8];
    const float* b2   = (const float*)d_in[9];
    const float* W3   = (const float*)d_in[10];
    const float* a3s  = (const float*)d_in[11];
    const float* a3d  = (const float*)d_in[12];
    const float* b3   = (const float*)d_in[13];
    const float* Wout = (const float*)d_in[14];
    const float* bout = (const float*)d_in[15];
    float* out = (float*)d_out;

    float *p_h, *p_x, *p_x3;
    cudaGetSymbolAddress((void**)&p_h,  g_h);
    cudaGetSymbolAddress((void**)&p_x,  g_x);
    cudaGetSymbolAddress((void**)&p_x3, g_x3);

    const int scan_blocks = (N_NODES + 1023) / 1024;   // 49

    // CSR build (identical for all layers)
    detect_kernel<<<1, 256>>>(ei);
    init_counts_kernel<<<(N_NODES + 255) / 256, 256>>>();
    count_kernel<<<(NE + 255) / 256, 256>>>(ei);
    scan_block_kernel<<<scan_blocks, 1024>>>();
    scan_mid_kernel<<<1, 32>>>(scan_blocks);
    scan_add_kernel<<<scan_blocks, 1024>>>();
    fill_kernel<<<(E_TOT + 255) / 256, 256>>>(ei);

    dim3 ggrid(HCDIM / BN, (N_NODES + BM - 1) / BM);
    int alpha_blocks = (N_NODES * NHEADS + 7) / 8;          // 8 warps/block
    int stats_blocks = (N_NODES + 31) / 32;                 // 8 warps * 4 nodes

    // ---- layer 1 ----
    gemm_kernel<<<ggrid, 256>>>(x, W1, p_h, N_NODES, F_IN, HCDIM);
    alpha_kernel<<<alpha_blocks, 256>>>(p_h, a1s, a1d);
    stats_kernel<<<stats_blocks, 256>>>();
    aggregate_kernel<<<N_NODES, 512>>>(p_h, b1, p_x, 0);

    // ---- layer 2 ----
    gemm_kernel<<<ggrid, 256>>>(p_x, W2, p_h, N_NODES, HCDIM, HCDIM);
    alpha_kernel<<<alpha_blocks, 256>>>(p_h, a2s, a2d);
    stats_kernel<<<stats_blocks, 256>>>();
    aggregate_kernel<<<N_NODES, 512>>>(p_h, b2, p_x, 0);

    // ---- layer 3 (mean over heads) ----
    gemm_kernel<<<ggrid, 256>>>(p_x, W3, p_h, N_NODES, HCDIM, HCDIM);
    alpha_kernel<<<alpha_blocks, 256>>>(p_h, a3s, a3d);
    stats_kernel<<<stats_blocks, 256>>>();
    aggregate_kernel<<<N_NODES, 512>>>(p_h, b3, p_x3, 1);

    // ---- output projection ----
    proj_kernel<<<(N_NODES + 15) / 16, 256>>>(p_x3, Wout, bout, out);
}

// round 2
// speedup vs baseline: 1.6683x; 1.6683x over previous
#include <cuda_runtime.h>
#include <math.h>

#define N_NODES 50000
#define F_IN    18
#define NHEADS  8
#define CDIM    64
#define HCDIM   512
#define NE      400000
#define E_TOT   (NE + N_NODES)
#define OUT_DIM 15
#define NEG_SLOPE 0.2f

// ---------------- scratch (static device globals; no runtime allocation) ----------------
__device__ float g_h [N_NODES * HCDIM];   // post-GEMM features of current layer
__device__ float g_x [N_NODES * HCDIM];   // layer activations (ping)
__device__ float g_x3[N_NODES * CDIM];    // layer-3 output (mean over heads)
__device__ float g_as[N_NODES * NHEADS];
__device__ float g_ad[N_NODES * NHEADS];
__device__ float g_alpha[(size_t)E_TOT * NHEADS];   // CSR-ordered e-values, then alpha
__device__ int   g_src_sorted[E_TOT];
__device__ int   g_rowptr[N_NODES + 1];
__device__ int   g_cursor[N_NODES];
__device__ int   g_counts[N_NODES];
__device__ int   g_part[64];
__device__ int   g_is64;

// ---------------- edge dtype handling ----------------
__device__ __forceinline__ int edge_at(const int* p, int idx) {
    return g_is64 ? p[2 * idx] : p[idx];
}

__global__ void detect_kernel(const int* __restrict__ p) {
    __shared__ int red[256];
    int acc = 0;
    for (int i = threadIdx.x; i < 8192; i += 256) acc |= p[2 * i + 1];
    red[threadIdx.x] = acc;
    __syncthreads();
    for (int s = 128; s > 0; s >>= 1) {
        if (threadIdx.x < s) red[threadIdx.x] |= red[threadIdx.x + s];
        __syncthreads();
    }
    if (threadIdx.x == 0) g_is64 = (red[0] == 0) ? 1 : 0;
}

// ---------------- CSR build ----------------
__global__ void init_counts_kernel() {
    int i = blockIdx.x * blockDim.x + threadIdx.x;
    if (i < N_NODES) g_counts[i] = 1;
}

__global__ void count_kernel(const int* __restrict__ ei) {
    int i = blockIdx.x * blockDim.x + threadIdx.x;
    if (i < NE) atomicAdd(&g_counts[edge_at(ei, NE + i)], 1);
}

__global__ void __launch_bounds__(1024) scan_block_kernel() {
    __shared__ int sm[1024];
    int i = blockIdx.x * 1024 + threadIdx.x;
    int v = (i < N_NODES) ? g_counts[i] : 0;
    sm[threadIdx.x] = v;
    __syncthreads();
    for (int off = 1; off < 1024; off <<= 1) {
        int t = (threadIdx.x >= off) ? sm[threadIdx.x - off] : 0;
        __syncthreads();
        sm[threadIdx.x] += t;
        __syncthreads();
    }
    if (i < N_NODES) g_rowptr[i] = sm[threadIdx.x] - v;
    if (threadIdx.x == 1023) g_part[blockIdx.x] = sm[1023];
}

__global__ void scan_mid_kernel(int nblocks) {
    if (threadIdx.x == 0) {
        int run = 0;
        for (int b = 0; b < nblocks; b++) { int t = g_part[b]; g_part[b] = run; run += t; }
    }
}

__global__ void __launch_bounds__(1024) scan_add_kernel() {
    int i = blockIdx.x * 1024 + threadIdx.x;
    if (i < N_NODES) {
        int v = g_rowptr[i] + g_part[blockIdx.x];
        g_rowptr[i] = v;
        g_cursor[i] = v;
    }
    if (i == 0) g_rowptr[N_NODES] = E_TOT;
}

__global__ void fill_kernel(const int* __restrict__ ei) {
    int i = blockIdx.x * blockDim.x + threadIdx.x;
    if (i >= E_TOT) return;
    int src, dst;
    if (i < NE) { src = edge_at(ei, i); dst = edge_at(ei, NE + i); }
    else        { src = dst = i - NE; }
    int pos = atomicAdd(&g_cursor[dst], 1);
    g_src_sorted[pos] = src;
}

// ---------------- small-K GEMM (layer 1, K=18) ----------------
#define BM 128
#define BN 64
#define BK 16

__global__ void __launch_bounds__(256) gemm_small_kernel(const float* __restrict__ A,
                                                         const float* __restrict__ B,
                                                         float* __restrict__ C,
                                                         int M, int K, int Nc) {
    __shared__ float As[BK][BM + 4];
    __shared__ float Bs[BK][BN + 4];
    int tid = threadIdx.x;
    int bn0 = blockIdx.x * BN;
    int bm0 = blockIdx.y * BM;
    int tr = tid >> 4;
    int tc = tid & 15;
    int a_row = tid >> 1;
    int a_cb  = (tid & 1) * 8;
    int b_row = tid >> 4;
    int b_col = (tid & 15) * 4;

    float acc[8][4];
#pragma unroll
    for (int i = 0; i < 8; i++)
#pragma unroll
        for (int j = 0; j < 4; j++) acc[i][j] = 0.f;

    for (int k0 = 0; k0 < K; k0 += BK) {
        int gm = bm0 + a_row;
#pragma unroll
        for (int i = 0; i < 8; i++) {
            int gk = k0 + a_cb + i;
            As[a_cb + i][a_row] = (gm < M && gk < K) ? A[(long long)gm * K + gk] : 0.f;
        }
        {
            int gk = k0 + b_row;
            float4 bv = make_float4(0.f, 0.f, 0.f, 0.f);
            if (gk < K) bv = *(const float4*)&B[(long long)gk * Nc + bn0 + b_col];
            *(float4*)&Bs[b_row][b_col] = bv;
        }
        __syncthreads();
#pragma unroll
        for (int kk = 0; kk < BK; kk++) {
            float a[8], b[4];
#pragma unroll
            for (int i = 0; i < 8; i++) a[i] = As[kk][tr * 8 + i];
#pragma unroll
            for (int j = 0; j < 4; j++) b[j] = Bs[kk][tc * 4 + j];
#pragma unroll
            for (int i = 0; i < 8; i++)
#pragma unroll
                for (int j = 0; j < 4; j++) acc[i][j] += a[i] * b[j];
        }
        __syncthreads();
    }
#pragma unroll
    for (int i = 0; i < 8; i++) {
        int gm = bm0 + tr * 8 + i;
        if (gm < M) {
#pragma unroll
            for (int j = 0; j < 4; j++)
                C[(long long)gm * Nc + bn0 + tc * 4 + j] = acc[i][j];
        }
    }
}

// ---------------- fast GEMM (layers 2/3, K=512): 128x128x16, double-buffered ----------------
#define GBM 128
#define GBN 128
#define GBK 16
#define GPAD 4

__global__ void __launch_bounds__(256) gemm128_kernel(const float* __restrict__ A,
                                                      const float* __restrict__ B,
                                                      float* __restrict__ C,
                                                      int M, int K, int Nc) {
    __shared__ float As[2][GBK][GBM + GPAD];
    __shared__ float Bs[2][GBK][GBN + GPAD];
    int tid = threadIdx.x;
    int tx = tid & 15, ty = tid >> 4;
    int bm0 = blockIdx.y * GBM;
    int bn0 = blockIdx.x * GBN;

    // A tile: 128 rows x 16 cols = 512 float4 (4 f4 per row along K)
    int am0 = tid >> 2;               // rows 0..63
    int ak  = (tid & 3) * 4;          // k offset 0,4,8,12
    int am1 = am0 + 64;               // rows 64..127
    // B tile: 16 rows x 128 cols = 512 float4 (32 f4 per row along N)
    int bk0 = tid >> 5;               // 0..7
    int bn4 = (tid & 31) * 4;
    int bk1 = bk0 + 8;                // 8..15

    bool a0ok = (bm0 + am0) < M;
    bool a1ok = (bm0 + am1) < M;
    const float* Arow0 = A + (long long)(bm0 + am0) * K + ak;
    const float* Arow1 = A + (long long)(bm0 + am1) * K + ak;
    const float* Brow0 = B + (long long)bk0 * Nc + bn0 + bn4;
    const float* Brow1 = B + (long long)bk1 * Nc + bn0 + bn4;

    float acc[8][8];
#pragma unroll
    for (int i = 0; i < 8; i++)
#pragma unroll
        for (int j = 0; j < 8; j++) acc[i][j] = 0.f;

    const float4 f4z = make_float4(0.f, 0.f, 0.f, 0.f);
    float4 pa0, pa1, pb0, pb1;

    int ntiles = K / GBK;

    // prefetch tile 0
    pa0 = a0ok ? *(const float4*)(Arow0) : f4z;
    pa1 = a1ok ? *(const float4*)(Arow1) : f4z;
    pb0 = *(const float4*)(Brow0);
    pb1 = *(const float4*)(Brow1);
    // store tile 0 into buf 0
    As[0][ak + 0][am0] = pa0.x; As[0][ak + 1][am0] = pa0.y;
    As[0][ak + 2][am0] = pa0.z; As[0][ak + 3][am0] = pa0.w;
    As[0][ak + 0][am1] = pa1.x; As[0][ak + 1][am1] = pa1.y;
    As[0][ak + 2][am1] = pa1.z; As[0][ak + 3][am1] = pa1.w;
    *(float4*)&Bs[0][bk0][bn4] = pb0;
    *(float4*)&Bs[0][bk1][bn4] = pb1;
    __syncthreads();

    for (int t = 0; t < ntiles; t++) {
        int buf = t & 1;
        if (t + 1 < ntiles) {
            long long koff = (long long)(t + 1) * GBK;
            pa0 = a0ok ? *(const float4*)(Arow0 + koff) : f4z;
            pa1 = a1ok ? *(const float4*)(Arow1 + koff) : f4z;
            pb0 = *(const float4*)(Brow0 + koff * Nc);
            pb1 = *(const float4*)(Brow1 + koff * Nc);
        }
#pragma unroll
        for (int kk = 0; kk < GBK; kk++) {
            float4 a0 = *(const float4*)&As[buf][kk][ty * 4];
            float4 a1 = *(const float4*)&As[buf][kk][64 + ty * 4];
            float4 b0 = *(const float4*)&Bs[buf][kk][tx * 4];
            float4 b1 = *(const float4*)&Bs[buf][kk][64 + tx * 4];
            float av[8] = {a0.x, a0.y, a0.z, a0.w, a1.x, a1.y, a1.z, a1.w};
            float bv[8] = {b0.x, b0.y, b0.z, b0.w, b1.x, b1.y, b1.z, b1.w};
#pragma unroll
            for (int i = 0; i < 8; i++)
#pragma unroll
                for (int j = 0; j < 8; j++) acc[i][j] += av[i] * bv[j];
        }
        if (t + 1 < ntiles) {
            int nb = buf ^ 1;
            As[nb][ak + 0][am0] = pa0.x; As[nb][ak + 1][am0] = pa0.y;
            As[nb][ak + 2][am0] = pa0.z; As[nb][ak + 3][am0] = pa0.w;
            As[nb][ak + 0][am1] = pa1.x; As[nb][ak + 1][am1] = pa1.y;
            As[nb][ak + 2][am1] = pa1.z; As[nb][ak + 3][am1] = pa1.w;
            *(float4*)&Bs[nb][bk0][bn4] = pb0;
            *(float4*)&Bs[nb][bk1][bn4] = pb1;
        }
        __syncthreads();
    }

    // store C: rows ty*4+i (i<4) and 64+ty*4+i; cols tx*4 and 64+tx*4 (float4)
#pragma unroll
    for (int half = 0; half < 2; half++) {
#pragma unroll
        for (int i = 0; i < 4; i++) {
            int gm = bm0 + half * 64 + ty * 4 + i;
            if (gm < M) {
                int r = half * 4 + i;
                float4 c0 = make_float4(acc[r][0], acc[r][1], acc[r][2], acc[r][3]);
                float4 c1 = make_float4(acc[r][4], acc[r][5], acc[r][6], acc[r][7]);
                *(float4*)&C[(long long)gm * Nc + bn0 + tx * 4]      = c0;
                *(float4*)&C[(long long)gm * Nc + bn0 + 64 + tx * 4] = c1;
            }
        }
    }
}

// ---------------- alpha_s / alpha_d ----------------
__global__ void alpha_kernel(const float* __restrict__ h,
                             const float* __restrict__ a_src,
                             const float* __restrict__ a_dst) {
    int wid = (blockIdx.x * blockDim.x + threadIdx.x) >> 5;
    int lane = threadIdx.x & 31;
    if (wid >= N_NODES * NHEADS) return;
    int n = wid >> 3, hh = wid & 7;
    const float* hp = h + (long long)n * HCDIM + hh * CDIM;
    float v1 = hp[lane], v2 = hp[lane + 32];
    float s1 = a_src[hh * CDIM + lane], s2 = a_src[hh * CDIM + lane + 32];
    float d1 = a_dst[hh * CDIM + lane], d2 = a_dst[hh * CDIM + lane + 32];
    float as = v1 * s1 + v2 * s2;
    float ad = v1 * d1 + v2 * d2;
#pragma unroll
    for (int off = 16; off > 0; off >>= 1) {
        as += __shfl_xor_sync(0xffffffffu, as, off);
        ad += __shfl_xor_sync(0xffffffffu, ad, off);
    }
    if (lane == 0) {
        g_as[n * NHEADS + hh] = as;
        g_ad[n * NHEADS + hh] = ad;
    }
}

// ---------------- segment softmax (pass1: gather + store e; pass2: read e back) ----------------
__global__ void stats_kernel() {
    int lane = threadIdx.x & 31;
    int warp = (blockIdx.x * blockDim.x + threadIdx.x) >> 5;
    int sub = lane >> 3, hh = lane & 7;
    int n = warp * 4 + sub;
    if (n >= N_NODES) return;
    int row = g_rowptr[n], end = g_rowptr[n + 1];
    float ad = g_ad[n * NHEADS + hh];
    float m = -INFINITY, s = 0.f;
    for (int j = row; j < end; j++) {
        int src = g_src_sorted[j];
        float e = g_as[src * NHEADS + hh] + ad;
        e = (e > 0.f) ? e : NEG_SLOPE * e;
        g_alpha[(size_t)j * NHEADS + hh] = e;          // cache e for pass 2
        float nm = fmaxf(m, e);
        s = s * __expf(m - nm) + __expf(e - nm);
        m = nm;
    }
    float inv = 1.0f / (s + 1e-16f);
    for (int j = row; j < end; j++) {
        float e = g_alpha[(size_t)j * NHEADS + hh];    // coalesced read-back
        g_alpha[(size_t)j * NHEADS + hh] = __expf(e - m) * inv;
    }
}

// ---------------- heavy aggregation: float4 channels, 2-edge unroll ----------------
__global__ void __launch_bounds__(128) aggregate_kernel(const float* __restrict__ hin,
                                                        const float* __restrict__ bias,
                                                        float* __restrict__ outp,
                                                        int mode) {
    __shared__ float4 sm4[HCDIM / 4];
    int n = blockIdx.x;
    int tid = threadIdx.x;                    // 0..127, 4 channels each
    int head = tid >> 4;                      // 16 threads per head
    int row = g_rowptr[n], end = g_rowptr[n + 1];
    const float4* h4 = (const float4*)hin;
    float4 acc = make_float4(0.f, 0.f, 0.f, 0.f);
    int j = row;
    for (; j + 1 < end; j += 2) {
        int s0 = __ldg(&g_src_sorted[j]);
        int s1 = __ldg(&g_src_sorted[j + 1]);
        float a0 = __ldg(&g_alpha[(size_t)j * NHEADS + head]);
        float a1 = __ldg(&g_alpha[(size_t)(j + 1) * NHEADS + head]);
        float4 v0 = __ldg(&h4[(long long)s0 * (HCDIM / 4) + tid]);
        float4 v1 = __ldg(&h4[(long long)s1 * (HCDIM / 4) + tid]);
        acc.x = fmaf(a0, v0.x, fmaf(a1, v1.x, acc.x));
        acc.y = fmaf(a0, v0.y, fmaf(a1, v1.y, acc.y));
        acc.z = fmaf(a0, v0.z, fmaf(a1, v1.z, acc.z));
        acc.w = fmaf(a0, v0.w, fmaf(a1, v1.w, acc.w));
    }
    if (j < end) {
        int s0 = __ldg(&g_src_sorted[j]);
        float a0 = __ldg(&g_alpha[(size_t)j * NHEADS + head]);
        float4 v0 = __ldg(&h4[(long long)s0 * (HCDIM / 4) + tid]);
        acc.x = fmaf(a0, v0.x, acc.x);
        acc.y = fmaf(a0, v0.y, acc.y);
        acc.z = fmaf(a0, v0.z, acc.z);
        acc.w = fmaf(a0, v0.w, acc.w);
    }
    if (mode == 0) {
        float4 b4 = ((const float4*)bias)[tid];
        float4 o;
        float vx = acc.x + b4.x; o.x = (vx > 0.f) ? vx : expm1f(vx);
        float vy = acc.y + b4.y; o.y = (vy > 0.f) ? vy : expm1f(vy);
        float vz = acc.z + b4.z; o.z = (vz > 0.f) ? vz : expm1f(vz);
        float vw = acc.w + b4.w; o.w = (vw > 0.f) ? vw : expm1f(vw);
        ((float4*)outp)[(long long)n * (HCDIM / 4) + tid] = o;
    } else {
        sm4[tid] = acc;
        __syncthreads();
        if (tid < 16) {
            float4 s = make_float4(0.f, 0.f, 0.f, 0.f);
#pragma unroll
            for (int hh = 0; hh < NHEADS; hh++) {
                float4 f = sm4[hh * 16 + tid];
                s.x += f.x; s.y += f.y; s.z += f.z; s.w += f.w;
            }
            float4 b4 = ((const float4*)bias)[tid];
            float4 o;
            o.x = s.x * (1.0f / NHEADS) + b4.x;
            o.y = s.y * (1.0f / NHEADS) + b4.y;
            o.z = s.z * (1.0f / NHEADS) + b4.z;
            o.w = s.w * (1.0f / NHEADS) + b4.w;
            ((float4*)outp)[(long long)n * (CDIM / 4) + tid] = o;
        }
    }
}

// ---------------- final projection ----------------
__global__ void __launch_bounds__(256) proj_kernel(const float* __restrict__ x3,
                                                   const float* __restrict__ Wout,
                                                   const float* __restrict__ bout,
                                                   float* __restrict__ out) {
    __shared__ float Ws[CDIM * 16];
    __shared__ float bs[16];
    int tid = threadIdx.x;
    for (int idx = tid; idx < CDIM * 16; idx += 256) {
        int c = idx >> 4, o = idx & 15;
        Ws[idx] = (o < OUT_DIM) ? Wout[c * OUT_DIM + o] : 0.f;
    }
    if (tid < 16) bs[tid] = (tid < OUT_DIM) ? bout[tid] : 0.f;
    __syncthreads();
    int tx = tid & 15;
    int tn = tid >> 4;
    int n = blockIdx.x * 16 + tn;
    if (n >= N_NODES) return;
    const float* xr = x3 + (long long)n * CDIM;
    float acc = 0.f;
#pragma unroll
    for (int c = 0; c < CDIM; c++) acc += xr[c] * Ws[c * 16 + tx];
    if (tx < OUT_DIM) out[(long long)n * OUT_DIM + tx] = acc + bs[tx];
}

// ---------------- launch ----------------
extern "C" void kernel_launch(void* const* d_in, const int* in_sizes, int n_in,
                              void* d_out, int out_size) {
    const float* x    = (const float*)d_in[0];
    const int*   ei   = (const int*)d_in[1];
    const float* W1   = (const float*)d_in[2];
    const float* a1s  = (const float*)d_in[3];
    const float* a1d  = (const float*)d_in[4];
    const float* b1   = (const float*)d_in[5];
    const float* W2   = (const float*)d_in[6];
    const float* a2s  = (const float*)d_in[7];
    const float* a2d  = (const float*)d_in[8];
    const float* b2   = (const float*)d_in[9];
    const float* W3   = (const float*)d_in[10];
    const float* a3s  = (const float*)d_in[11];
    const float* a3d  = (const float*)d_in[12];
    const float* b3   = (const float*)d_in[13];
    const float* Wout = (const float*)d_in[14];
    const float* bout = (const float*)d_in[15];
    float* out = (float*)d_out;

    float *p_h, *p_x, *p_x3;
    cudaGetSymbolAddress((void**)&p_h,  g_h);
    cudaGetSymbolAddress((void**)&p_x,  g_x);
    cudaGetSymbolAddress((void**)&p_x3, g_x3);

    const int scan_blocks = (N_NODES + 1023) / 1024;

    detect_kernel<<<1, 256>>>(ei);
    init_counts_kernel<<<(N_NODES + 255) / 256, 256>>>();
    count_kernel<<<(NE + 255) / 256, 256>>>(ei);
    scan_block_kernel<<<scan_blocks, 1024>>>();
    scan_mid_kernel<<<1, 32>>>(scan_blocks);
    scan_add_kernel<<<scan_blocks, 1024>>>();
    fill_kernel<<<(E_TOT + 255) / 256, 256>>>(ei);

    dim3 sgrid(HCDIM / BN, (N_NODES + BM - 1) / BM);
    dim3 fgrid(HCDIM / GBN, (N_NODES + GBM - 1) / GBM);
    int alpha_blocks = (N_NODES * NHEADS + 7) / 8;
    int stats_blocks = (N_NODES + 31) / 32;

    // ---- layer 1 ----
    gemm_small_kernel<<<sgrid, 256>>>(x, W1, p_h, N_NODES, F_IN, HCDIM);
    alpha_kernel<<<alpha_blocks, 256>>>(p_h, a1s, a1d);
    stats_kernel<<<stats_blocks, 256>>>();
    aggregate_kernel<<<N_NODES, 128>>>(p_h, b1, p_x, 0);

    // ---- layer 2 ----
    gemm128_kernel<<<fgrid, 256>>>(p_x, W2, p_h, N_NODES, HCDIM, HCDIM);
    alpha_kernel<<<alpha_blocks, 256>>>(p_h, a2s, a2d);
    stats_kernel<<<stats_blocks, 256>>>();
    aggregate_kernel<<<N_NODES, 128>>>(p_h, b2, p_x, 0);

    // ---- layer 3 ----
    gemm128_kernel<<<fgrid, 256>>>(p_x, W3, p_h, N_NODES, HCDIM, HCDIM);
    alpha_kernel<<<alpha_blocks, 256>>>(p_h, a3s, a3d);
    stats_kernel<<<stats_blocks, 256>>>();
    aggregate_kernel<<<N_NODES, 128>>>(p_h, b3, p_x3, 1);

    // ---- output projection ----
    proj_kernel<<<(N_NODES + 15) / 16, 256>>>(p_x3, Wout, bout, out);
}

// round 6
// speedup vs baseline: 2.6528x; 1.5902x over previous
#include <cuda_runtime.h>
#include <cuda_bf16.h>
#include <cstdint>
#include <stdint.h>
#include <math.h>

#define N_NODES 50000
#define F_IN    18
#define NHEADS  8
#define CDIM    64
#define HCDIM   512
#define NE      400000
#define E_TOT   (NE + N_NODES)
#define OUT_DIM 15
#define NEG_SLOPE 0.2f

// ---------------- scratch (static device globals; no runtime allocation) ----------------
__device__ float g_h [N_NODES * HCDIM];          // post-GEMM features of current layer
__device__ float g_x3[N_NODES * CDIM];           // layer-3 output (mean over heads)
__device__ __nv_bfloat16 g_xhi[N_NODES * HCDIM]; // activation hi part (GEMM A operand)
__device__ __nv_bfloat16 g_xlo[N_NODES * HCDIM]; // activation lo part
__device__ __nv_bfloat16 g_w2hi[HCDIM * HCDIM];  // W2 hi, native [K][N]
__device__ __nv_bfloat16 g_w2lo[HCDIM * HCDIM];
__device__ __nv_bfloat16 g_w3hi[HCDIM * HCDIM];
__device__ __nv_bfloat16 g_w3lo[HCDIM * HCDIM];
__device__ float g_as[N_NODES * NHEADS];
__device__ float g_ad[N_NODES * NHEADS];
__device__ float g_alpha[(size_t)E_TOT * NHEADS];
__device__ int   g_src_sorted[E_TOT];
__device__ int   g_rowptr[N_NODES + 1];
__device__ int   g_cursor[N_NODES];
__device__ int   g_counts[N_NODES];
__device__ int   g_part[64];
__device__ int   g_is64;

// ---------------- PTX helpers (portable: sm_80-era features only) ----------------
__device__ __forceinline__ uint32_t smem_u32(const void* p) {
    uint32_t a;
    asm("{ .reg .u64 t; cvta.to.shared.u64 t, %1; cvt.u32.u64 %0, t; }" : "=r"(a) : "l"(p));
    return a;
}
static __device__ __forceinline__ void cp_async16(uint32_t dst, const void* src, int sz) {
    asm volatile("cp.async.cg.shared.global [%0], [%1], 16, %2;\n"
                 :: "r"(dst), "l"(src), "r"(sz) : "memory");
}
static __device__ __forceinline__ void cp_commit() {
    asm volatile("cp.async.commit_group;" ::: "memory");
}
static __device__ __forceinline__ void cp_wait0() {
    asm volatile("cp.async.wait_group 0;" ::: "memory");
}
static __device__ __forceinline__ void cp_wait1() {
    asm volatile("cp.async.wait_group 1;" ::: "memory");
}

#define LDSM_X4(r, addr) \
    asm volatile("ldmatrix.sync.aligned.m8n8.x4.shared.b16 {%0,%1,%2,%3}, [%4];" \
        : "=r"((r)[0]), "=r"((r)[1]), "=r"((r)[2]), "=r"((r)[3]) : "r"(addr))
// B operand: [K,N] k-row-major tile -> column fragments via TRANS ldmatrix
#define LDSM_X2_TRANS(r, addr) \
    asm volatile("ldmatrix.sync.aligned.m8n8.x2.trans.shared.b16 {%0,%1}, [%2];" \
        : "=r"((r)[0]), "=r"((r)[1]) : "r"(addr))
#define MMA_BF16(c, a, b) \
    asm volatile("mma.sync.aligned.m16n8k16.row.col.f32.bf16.bf16.f32 " \
        "{%0,%1,%2,%3},{%4,%5,%6,%7},{%8,%9},{%0,%1,%2,%3};" \
        : "+f"((c)[0]), "+f"((c)[1]), "+f"((c)[2]), "+f"((c)[3]) \
        : "r"((a)[0]), "r"((a)[1]), "r"((a)[2]), "r"((a)[3]), "r"((b)[0]), "r"((b)[1]))

// ---------------- edge dtype handling ----------------
__device__ __forceinline__ int edge_at(const int* p, int idx) {
    return g_is64 ? p[2 * idx] : p[idx];
}

__global__ void detect_kernel(const int* __restrict__ p) {
    __shared__ int red[256];
    int acc = 0;
    for (int i = threadIdx.x; i < 8192; i += 256) acc |= p[2 * i + 1];
    red[threadIdx.x] = acc;
    __syncthreads();
    for (int s = 128; s > 0; s >>= 1) {
        if (threadIdx.x < s) red[threadIdx.x] |= red[threadIdx.x + s];
        __syncthreads();
    }
    if (threadIdx.x == 0) g_is64 = (red[0] == 0) ? 1 : 0;
}

// ---------------- CSR build ----------------
__global__ void init_counts_kernel() {
    int i = blockIdx.x * blockDim.x + threadIdx.x;
    if (i < N_NODES) g_counts[i] = 1;
}
__global__ void count_kernel(const int* __restrict__ ei) {
    int i = blockIdx.x * blockDim.x + threadIdx.x;
    if (i < NE) atomicAdd(&g_counts[edge_at(ei, NE + i)], 1);
}
__global__ void __launch_bounds__(1024) scan_block_kernel() {
    __shared__ int sm[1024];
    int i = blockIdx.x * 1024 + threadIdx.x;
    int v = (i < N_NODES) ? g_counts[i] : 0;
    sm[threadIdx.x] = v;
    __syncthreads();
    for (int off = 1; off < 1024; off <<= 1) {
        int t = (threadIdx.x >= off) ? sm[threadIdx.x - off] : 0;
        __syncthreads();
        sm[threadIdx.x] += t;
        __syncthreads();
    }
    if (i < N_NODES) g_rowptr[i] = sm[threadIdx.x] - v;
    if (threadIdx.x == 1023) g_part[blockIdx.x] = sm[1023];
}
__global__ void scan_mid_kernel(int nblocks) {
    if (threadIdx.x == 0) {
        int run = 0;
        for (int b = 0; b < nblocks; b++) { int t = g_part[b]; g_part[b] = run; run += t; }
    }
}
__global__ void __launch_bounds__(1024) scan_add_kernel() {
    int i = blockIdx.x * 1024 + threadIdx.x;
    if (i < N_NODES) {
        int v = g_rowptr[i] + g_part[blockIdx.x];
        g_rowptr[i] = v;
        g_cursor[i] = v;
    }
    if (i == 0) g_rowptr[N_NODES] = E_TOT;
}
__global__ void fill_kernel(const int* __restrict__ ei) {
    int i = blockIdx.x * blockDim.x + threadIdx.x;
    if (i >= E_TOT) return;
    int src, dst;
    if (i < NE) { src = edge_at(ei, i); dst = edge_at(ei, NE + i); }
    else        { src = dst = i - NE; }
    int pos = atomicAdd(&g_cursor[dst], 1);
    g_src_sorted[pos] = src;
}

// ---------------- small-K GEMM (layer 1, K=18) ----------------
#define BM 128
#define BN 64
#define BK 16

__global__ void __launch_bounds__(256) gemm_small_kernel(const float* __restrict__ A,
                                                         const float* __restrict__ B,
                                                         float* __restrict__ C,
                                                         int M, int K, int Nc) {
    __shared__ float As[BK][BM + 4];
    __shared__ float Bs[BK][BN + 4];
    int tid = threadIdx.x;
    int bn0 = blockIdx.x * BN;
    int bm0 = blockIdx.y * BM;
    int tr = tid >> 4;
    int tc = tid & 15;
    int a_row = tid >> 1;
    int a_cb  = (tid & 1) * 8;
    int b_row = tid >> 4;
    int b_col = (tid & 15) * 4;

    float acc[8][4];
#pragma unroll
    for (int i = 0; i < 8; i++)
#pragma unroll
        for (int j = 0; j < 4; j++) acc[i][j] = 0.f;

    for (int k0 = 0; k0 < K; k0 += BK) {
        int gm = bm0 + a_row;
#pragma unroll
        for (int i = 0; i < 8; i++) {
            int gk = k0 + a_cb + i;
            As[a_cb + i][a_row] = (gm < M && gk < K) ? A[(long long)gm * K + gk] : 0.f;
        }
        {
            int gk = k0 + b_row;
            float4 bv = make_float4(0.f, 0.f, 0.f, 0.f);
            if (gk < K) bv = *(const float4*)&B[(long long)gk * Nc + bn0 + b_col];
            *(float4*)&Bs[b_row][b_col] = bv;
        }
        __syncthreads();
#pragma unroll
        for (int kk = 0; kk < BK; kk++) {
            float a[8], b[4];
#pragma unroll
            for (int i = 0; i < 8; i++) a[i] = As[kk][tr * 8 + i];
#pragma unroll
            for (int j = 0; j < 4; j++) b[j] = Bs[kk][tc * 4 + j];
#pragma unroll
            for (int i = 0; i < 8; i++)
#pragma unroll
                for (int j = 0; j < 4; j++) acc[i][j] += a[i] * b[j];
        }
        __syncthreads();
    }
#pragma unroll
    for (int i = 0; i < 8; i++) {
        int gm = bm0 + tr * 8 + i;
        if (gm < M) {
#pragma unroll
            for (int j = 0; j < 4; j++)
                C[(long long)gm * Nc + bn0 + tc * 4 + j] = acc[i][j];
        }
    }
}

// ---------------- W bf16 split (elementwise, native [K][N] layout kept) ----------------
__global__ void __launch_bounds__(256) wsplit_kernel(const float* __restrict__ W,
                                                     __nv_bfloat16* __restrict__ whi,
                                                     __nv_bfloat16* __restrict__ wlo) {
    int i = blockIdx.x * blockDim.x + threadIdx.x;
    if (i < HCDIM * HCDIM) {
        float v = W[i];
        __nv_bfloat16 hi = __float2bfloat16_rn(v);
        whi[i] = hi;
        wlo[i] = __float2bfloat16_rn(v - __bfloat162float(hi));
    }
}

// ---------------- mma.sync bf16-split GEMM: C[M,512] = X @ W ----------------
// A: Xhi/Xlo [M,K] bf16 row-major (K contiguous). B: Whi/Wlo [K,N] bf16 (N contiguous).
// Block tile 128x64, BK=32, 8 warps (warp tile 32x32), double-buffered cp.async.
// 3 products per fragment pair: AhiBhi + AhiBlo + AloBhi (fp32 accumulate).
#define KTILES  (HCDIM / 32)      // 16
#define APITCH  80                // 32 bf16 = 64 B + 16 B pad
#define BPITCH  144               // 64 bf16 = 128 B + 16 B pad
#define A_TB    (128 * APITCH)    // 10240
#define B_TB    (32 * BPITCH)     // 4608
#define BUF_B   (2 * A_TB + 2 * B_TB)   // 29696
#define GSMEM   (2 * BUF_B)       // 59392

__global__ void __launch_bounds__(256, 2)
mma_gemm_kernel(const __nv_bfloat16* __restrict__ Ahi,
                const __nv_bfloat16* __restrict__ Alo,
                const __nv_bfloat16* __restrict__ Whi,
                const __nv_bfloat16* __restrict__ Wlo,
                float* __restrict__ C, int M) {
    extern __shared__ char smem[];
    uint32_t sb = smem_u32(smem);
    int tid = threadIdx.x, lane = tid & 31, wid = tid >> 5;
    int wm = wid & 3, wn = wid >> 2;            // 4 x 2 warps -> 128 x 64
    int bm0 = blockIdx.y * 128, bn0 = blockIdx.x * 64;

    float acc[2][4][4];
#pragma unroll
    for (int im = 0; im < 2; im++)
#pragma unroll
        for (int in_ = 0; in_ < 4; in_++)
#pragma unroll
            for (int q = 0; q < 4; q++) acc[im][in_][q] = 0.f;

    auto load_tile = [&](int kt, int b) {
        uint32_t base = sb + (uint32_t)b * BUF_B;
        // A tiles: 128 rows x 64B (4 chunks) = 512 chunks per matrix
#pragma unroll
        for (int m = 0; m < 2; m++) {
            const __nv_bfloat16* srcm = m ? Alo : Ahi;
            uint32_t tb = base + (uint32_t)m * A_TB;
#pragma unroll
            for (int q = 0; q < 2; q++) {
                int idx = q * 256 + tid;
                int r = idx >> 2, ch = idx & 3;
                int gr = bm0 + r;
                int sz = 16;
                if (gr >= M) { gr = 0; sz = 0; }
                cp_async16(tb + (uint32_t)(r * APITCH + ch * 16),
                           srcm + (size_t)gr * HCDIM + kt * 32 + ch * 8, sz);
            }
        }
        // B tiles: 32 k-rows x 128B (8 chunks) = 256 chunks per matrix
#pragma unroll
        for (int m = 0; m < 2; m++) {
            const __nv_bfloat16* srcm = m ? Wlo : Whi;
            uint32_t tb = base + 2 * A_TB + (uint32_t)m * B_TB;
            int r = tid >> 3, ch = tid & 7;
            cp_async16(tb + (uint32_t)(r * BPITCH + ch * 16),
                       srcm + (size_t)(kt * 32 + r) * HCDIM + bn0 + ch * 8, 16);
        }
        cp_commit();
    };

    load_tile(0, 0);

    for (int t = 0; t < KTILES; t++) {
        int b = t & 1;
        if (t + 1 < KTILES) { load_tile(t + 1, b ^ 1); cp_wait1(); }
        else cp_wait0();
        __syncthreads();

        uint32_t abase = sb + (uint32_t)b * BUF_B;
        uint32_t bbase = abase + 2 * A_TB;
#pragma unroll
        for (int ks = 0; ks < 2; ks++) {
            uint32_t ah[2][4], al[2][4];
#pragma unroll
            for (int im = 0; im < 2; im++) {
                uint32_t ra = abase
                    + (uint32_t)((wm * 32 + im * 16 + (lane & 15)) * APITCH
                                 + (ks * 16 + (lane >> 4) * 8) * 2);
                LDSM_X4(ah[im], ra);
                LDSM_X4(al[im], ra + A_TB);
            }
#pragma unroll
            for (int in_ = 0; in_ < 4; in_++) {
                uint32_t rb = bbase
                    + (uint32_t)((ks * 16 + (lane & 15)) * BPITCH
                                 + (wn * 32 + in_ * 8) * 2);
                uint32_t bh[2], bl[2];
                LDSM_X2_TRANS(bh, rb);
                LDSM_X2_TRANS(bl, rb + B_TB);
#pragma unroll
                for (int im = 0; im < 2; im++) {
                    MMA_BF16(acc[im][in_], ah[im], bh);
                    MMA_BF16(acc[im][in_], ah[im], bl);
                    MMA_BF16(acc[im][in_], al[im], bh);
                }
            }
        }
        __syncthreads();
    }

    // epilogue: c frag rows lane/4 and lane/4+8, cols (lane%4)*2, +1
#pragma unroll
    for (int im = 0; im < 2; im++) {
        int r0 = bm0 + wm * 32 + im * 16 + (lane >> 2);
#pragma unroll
        for (int in_ = 0; in_ < 4; in_++) {
            int col = bn0 + wn * 32 + in_ * 8 + (lane & 3) * 2;
            if (r0 < M)
                *(float2*)&C[(size_t)r0 * HCDIM + col] =
                    make_float2(acc[im][in_][0], acc[im][in_][1]);
            if (r0 + 8 < M)
                *(float2*)&C[(size_t)(r0 + 8) * HCDIM + col] =
                    make_float2(acc[im][in_][2], acc[im][in_][3]);
        }
    }
}

// ---------------- alpha_s / alpha_d ----------------
__global__ void alpha_kernel(const float* __restrict__ h,
                             const float* __restrict__ a_src,
                             const float* __restrict__ a_dst) {
    int wid = (blockIdx.x * blockDim.x + threadIdx.x) >> 5;
    int lane = threadIdx.x & 31;
    if (wid >= N_NODES * NHEADS) return;
    int n = wid >> 3, hh = wid & 7;
    const float* hp = h + (long long)n * HCDIM + hh * CDIM;
    float v1 = hp[lane], v2 = hp[lane + 32];
    float s1 = a_src[hh * CDIM + lane], s2 = a_src[hh * CDIM + lane + 32];
    float d1 = a_dst[hh * CDIM + lane], d2 = a_dst[hh * CDIM + lane + 32];
    float as = v1 * s1 + v2 * s2;
    float ad = v1 * d1 + v2 * d2;
#pragma unroll
    for (int off = 16; off > 0; off >>= 1) {
        as += __shfl_xor_sync(0xffffffffu, as, off);
        ad += __shfl_xor_sync(0xffffffffu, ad, off);
    }
    if (lane == 0) {
        g_as[n * NHEADS + hh] = as;
        g_ad[n * NHEADS + hh] = ad;
    }
}

// ---------------- segment softmax ----------------
__global__ void stats_kernel() {
    int lane = threadIdx.x & 31;
    int warp = (blockIdx.x * blockDim.x + threadIdx.x) >> 5;
    int sub = lane >> 3, hh = lane & 7;
    int n = warp * 4 + sub;
    if (n >= N_NODES) return;
    int row = g_rowptr[n], end = g_rowptr[n + 1];
    float ad = g_ad[n * NHEADS + hh];
    float m = -INFINITY, s = 0.f;
    for (int j = row; j < end; j++) {
        int src = g_src_sorted[j];
        float e = g_as[src * NHEADS + hh] + ad;
        e = (e > 0.f) ? e : NEG_SLOPE * e;
        g_alpha[(size_t)j * NHEADS + hh] = e;
        float nm = fmaxf(m, e);
        s = s * __expf(m - nm) + __expf(e - nm);
        m = nm;
    }
    float inv = 1.0f / (s + 1e-16f);
    for (int j = row; j < end; j++) {
        float e = g_alpha[(size_t)j * NHEADS + hh];
        g_alpha[(size_t)j * NHEADS + hh] = __expf(e - m) * inv;
    }
}

// ---------------- heavy aggregation ----------------
__device__ __forceinline__ uint32_t pack_bf2(float a, float b) {
    __nv_bfloat162 t;
    t.x = __float2bfloat16_rn(a);
    t.y = __float2bfloat16_rn(b);
    return *(uint32_t*)&t;
}

__global__ void __launch_bounds__(128) aggregate_kernel(const float* __restrict__ hin,
                                                        const float* __restrict__ bias,
                                                        __nv_bfloat16* __restrict__ xhi,
                                                        __nv_bfloat16* __restrict__ xlo,
                                                        float* __restrict__ outp,
                                                        int mode) {
    __shared__ float4 sm4[HCDIM / 4];
    int n = blockIdx.x;
    int tid = threadIdx.x;
    int head = tid >> 4;
    int row = g_rowptr[n], end = g_rowptr[n + 1];
    const float4* h4 = (const float4*)hin;
    float4 acc = make_float4(0.f, 0.f, 0.f, 0.f);
    int j = row;
    for (; j + 1 < end; j += 2) {
        int s0 = __ldg(&g_src_sorted[j]);
        int s1 = __ldg(&g_src_sorted[j + 1]);
        float a0 = __ldg(&g_alpha[(size_t)j * NHEADS + head]);
        float a1 = __ldg(&g_alpha[(size_t)(j + 1) * NHEADS + head]);
        float4 v0 = __ldg(&h4[(long long)s0 * (HCDIM / 4) + tid]);
        float4 v1 = __ldg(&h4[(long long)s1 * (HCDIM / 4) + tid]);
        acc.x = fmaf(a0, v0.x, fmaf(a1, v1.x, acc.x));
        acc.y = fmaf(a0, v0.y, fmaf(a1, v1.y, acc.y));
        acc.z = fmaf(a0, v0.z, fmaf(a1, v1.z, acc.z));
        acc.w = fmaf(a0, v0.w, fmaf(a1, v1.w, acc.w));
    }
    if (j < end) {
        int s0 = __ldg(&g_src_sorted[j]);
        float a0 = __ldg(&g_alpha[(size_t)j * NHEADS + head]);
        float4 v0 = __ldg(&h4[(long long)s0 * (HCDIM / 4) + tid]);
        acc.x = fmaf(a0, v0.x, acc.x);
        acc.y = fmaf(a0, v0.y, acc.y);
        acc.z = fmaf(a0, v0.z, acc.z);
        acc.w = fmaf(a0, v0.w, acc.w);
    }
    if (mode == 0) {
        float4 b4 = ((const float4*)bias)[tid];
        float vx = acc.x + b4.x; vx = (vx > 0.f) ? vx : expm1f(vx);
        float vy = acc.y + b4.y; vy = (vy > 0.f) ? vy : expm1f(vy);
        float vz = acc.z + b4.z; vz = (vz > 0.f) ? vz : expm1f(vz);
        float vw = acc.w + b4.w; vw = (vw > 0.f) ? vw : expm1f(vw);
        __nv_bfloat16 hx = __float2bfloat16_rn(vx), hy = __float2bfloat16_rn(vy);
        __nv_bfloat16 hz = __float2bfloat16_rn(vz), hw = __float2bfloat16_rn(vw);
        float lx = vx - __bfloat162float(hx), ly = vy - __bfloat162float(hy);
        float lz = vz - __bfloat162float(hz), lw = vw - __bfloat162float(hw);
        size_t base = ((size_t)n * HCDIM + tid * 4) >> 1;   // uint32 index
        uint32_t* hip = (uint32_t*)xhi;
        uint32_t* lop = (uint32_t*)xlo;
        __nv_bfloat162 h01; h01.x = hx; h01.y = hy;
        __nv_bfloat162 h23; h23.x = hz; h23.y = hw;
        hip[base]     = *(uint32_t*)&h01;
        hip[base + 1] = *(uint32_t*)&h23;
        lop[base]     = pack_bf2(lx, ly);
        lop[base + 1] = pack_bf2(lz, lw);
    } else {
        sm4[tid] = acc;
        __syncthreads();
        if (tid < 16) {
            float4 s = make_float4(0.f, 0.f, 0.f, 0.f);
#pragma unroll
            for (int hh = 0; hh < NHEADS; hh++) {
                float4 f = sm4[hh * 16 + tid];
                s.x += f.x; s.y += f.y; s.z += f.z; s.w += f.w;
            }
            float4 b4 = ((const float4*)bias)[tid];
            float4 o;
            o.x = s.x * (1.0f / NHEADS) + b4.x;
            o.y = s.y * (1.0f / NHEADS) + b4.y;
            o.z = s.z * (1.0f / NHEADS) + b4.z;
            o.w = s.w * (1.0f / NHEADS) + b4.w;
            ((float4*)outp)[(long long)n * (CDIM / 4) + tid] = o;
        }
    }
}

// ---------------- final projection ----------------
__global__ void __launch_bounds__(256) proj_kernel(const float* __restrict__ x3,
                                                   const float* __restrict__ Wout,
                                                   const float* __restrict__ bout,
                                                   float* __restrict__ out) {
    __shared__ float Ws[CDIM * 16];
    __shared__ float bs[16];
    int tid = threadIdx.x;
    for (int idx = tid; idx < CDIM * 16; idx += 256) {
        int c = idx >> 4, o = idx & 15;
        Ws[idx] = (o < OUT_DIM) ? Wout[c * OUT_DIM + o] : 0.f;
    }
    if (tid < 16) bs[tid] = (tid < OUT_DIM) ? bout[tid] : 0.f;
    __syncthreads();
    int tx = tid & 15;
    int tn = tid >> 4;
    int n = blockIdx.x * 16 + tn;
    if (n >= N_NODES) return;
    const float* xr = x3 + (long long)n * CDIM;
    float acc = 0.f;
#pragma unroll
    for (int c = 0; c < CDIM; c++) acc += xr[c] * Ws[c * 16 + tx];
    if (tx < OUT_DIM) out[(long long)n * OUT_DIM + tx] = acc + bs[tx];
}

// ---------------- launch ----------------
extern "C" void kernel_launch(void* const* d_in, const int* in_sizes, int n_in,
                              void* d_out, int out_size) {
    const float* x    = (const float*)d_in[0];
    const int*   ei   = (const int*)d_in[1];
    const float* W1   = (const float*)d_in[2];
    const float* a1s  = (const float*)d_in[3];
    const float* a1d  = (const float*)d_in[4];
    const float* b1   = (const float*)d_in[5];
    const float* W2   = (const float*)d_in[6];
    const float* a2s  = (const float*)d_in[7];
    const float* a2d  = (const float*)d_in[8];
    const float* b2   = (const float*)d_in[9];
    const float* W3   = (const float*)d_in[10];
    const float* a3s  = (const float*)d_in[11];
    const float* a3d  = (const float*)d_in[12];
    const float* b3   = (const float*)d_in[13];
    const float* Wout = (const float*)d_in[14];
    const float* bout = (const float*)d_in[15];
    float* out = (float*)d_out;

    float *p_h, *p_x3;
    __nv_bfloat16 *p_xhi, *p_xlo, *p_w2hi, *p_w2lo, *p_w3hi, *p_w3lo;
    cudaGetSymbolAddress((void**)&p_h,    g_h);
    cudaGetSymbolAddress((void**)&p_x3,   g_x3);
    cudaGetSymbolAddress((void**)&p_xhi,  g_xhi);
    cudaGetSymbolAddress((void**)&p_xlo,  g_xlo);
    cudaGetSymbolAddress((void**)&p_w2hi, g_w2hi);
    cudaGetSymbolAddress((void**)&p_w2lo, g_w2lo);
    cudaGetSymbolAddress((void**)&p_w3hi, g_w3hi);
    cudaGetSymbolAddress((void**)&p_w3lo, g_w3lo);

    cudaFuncSetAttribute(mma_gemm_kernel, cudaFuncAttributeMaxDynamicSharedMemorySize, GSMEM);

    const int scan_blocks = (N_NODES + 1023) / 1024;

    detect_kernel<<<1, 256>>>(ei);
    init_counts_kernel<<<(N_NODES + 255) / 256, 256>>>();
    count_kernel<<<(NE + 255) / 256, 256>>>(ei);
    scan_block_kernel<<<scan_blocks, 1024>>>();
    scan_mid_kernel<<<1, 32>>>(scan_blocks);
    scan_add_kernel<<<scan_blocks, 1024>>>();
    fill_kernel<<<(E_TOT + 255) / 256, 256>>>(ei);

    // W2/W3 bf16 split (elementwise, layout preserved)
    int wsplit_blocks = (HCDIM * HCDIM + 255) / 256;
    wsplit_kernel<<<wsplit_blocks, 256>>>(W2, p_w2hi, p_w2lo);
    wsplit_kernel<<<wsplit_blocks, 256>>>(W3, p_w3hi, p_w3lo);

    dim3 sgrid(HCDIM / BN, (N_NODES + BM - 1) / BM);
    dim3 mgrid(HCDIM / 64, (N_NODES + 127) / 128);
    int alpha_blocks = (N_NODES * NHEADS + 7) / 8;
    int stats_blocks = (N_NODES + 31) / 32;

    // ---- layer 1 ----
    gemm_small_kernel<<<sgrid, 256>>>(x, W1, p_h, N_NODES, F_IN, HCDIM);
    alpha_kernel<<<alpha_blocks, 256>>>(p_h, a1s, a1d);
    stats_kernel<<<stats_blocks, 256>>>();
    aggregate_kernel<<<N_NODES, 128>>>(p_h, b1, p_xhi, p_xlo, nullptr, 0);

    // ---- layer 2 (mma.sync bf16-split GEMM) ----
    mma_gemm_kernel<<<mgrid, 256, GSMEM>>>(p_xhi, p_xlo, p_w2hi, p_w2lo, p_h, N_NODES);
    alpha_kernel<<<alpha_blocks, 256>>>(p_h, a2s, a2d);
    stats_kernel<<<stats_blocks, 256>>>();
    aggregate_kernel<<<N_NODES, 128>>>(p_h, b2, p_xhi, p_xlo, nullptr, 0);

    // ---- layer 3 ----
    mma_gemm_kernel<<<mgrid, 256, GSMEM>>>(p_xhi, p_xlo, p_w3hi, p_w3lo, p_h, N_NODES);
    alpha_kernel<<<alpha_blocks, 256>>>(p_h, a3s, a3d);
    stats_kernel<<<stats_blocks, 256>>>();
    aggregate_kernel<<<N_NODES, 128>>>(p_h, b3, nullptr, nullptr, p_x3, 1);

    // ---- output projection ----
    proj_kernel<<<(N_NODES + 15) / 16, 256>>>(p_x3, Wout, bout, out);
}

// round 7
// speedup vs baseline: 3.0989x; 1.1682x over previous
#include <cuda_runtime.h>
#include <cuda_bf16.h>
#include <cstdint>
#include <stdint.h>
#include <math.h>

#define N_NODES 50000
#define F_IN    18
#define NHEADS  8
#define CDIM    64
#define HCDIM   512
#define NE      400000
#define E_TOT   (NE + N_NODES)
#define OUT_DIM 15
#define NEG_SLOPE 0.2f

// ---------------- scratch (static device globals; no runtime allocation) ----------------
__device__ float g_h [N_NODES * HCDIM];          // post-GEMM features of current layer
__device__ float g_x3[N_NODES * CDIM];           // layer-3 output (mean over heads)
__device__ __nv_bfloat16 g_xhi[N_NODES * HCDIM]; // activation hi part (GEMM A operand)
__device__ __nv_bfloat16 g_xlo[N_NODES * HCDIM]; // activation lo part
__device__ __nv_bfloat16 g_w2hi[HCDIM * HCDIM];  // W2 hi, native [K][N]
__device__ __nv_bfloat16 g_w2lo[HCDIM * HCDIM];
__device__ __nv_bfloat16 g_w3hi[HCDIM * HCDIM];
__device__ __nv_bfloat16 g_w3lo[HCDIM * HCDIM];
__device__ float g_as[N_NODES * NHEADS];
__device__ float g_ad[N_NODES * NHEADS];
__device__ float g_alpha[(size_t)E_TOT * NHEADS];
__device__ int   g_src_sorted[E_TOT];
__device__ int   g_rowptr[N_NODES + 1];
__device__ int   g_cursor[N_NODES];
__device__ int   g_counts[N_NODES];
__device__ int   g_part[64];
__device__ int   g_is64;

// ---------------- PTX helpers (portable: sm_80-era features only) ----------------
__device__ __forceinline__ uint32_t smem_u32(const void* p) {
    uint32_t a;
    asm("{ .reg .u64 t; cvta.to.shared.u64 t, %1; cvt.u32.u64 %0, t; }" : "=r"(a) : "l"(p));
    return a;
}
static __device__ __forceinline__ void cp_async16(uint32_t dst, const void* src, int sz) {
    asm volatile("cp.async.cg.shared.global [%0], [%1], 16, %2;\n"
                 :: "r"(dst), "l"(src), "r"(sz) : "memory");
}
static __device__ __forceinline__ void cp_commit() {
    asm volatile("cp.async.commit_group;" ::: "memory");
}
static __device__ __forceinline__ void cp_wait0() {
    asm volatile("cp.async.wait_group 0;" ::: "memory");
}
static __device__ __forceinline__ void cp_wait1() {
    asm volatile("cp.async.wait_group 1;" ::: "memory");
}

#define LDSM_X4(r, addr) \
    asm volatile("ldmatrix.sync.aligned.m8n8.x4.shared.b16 {%0,%1,%2,%3}, [%4];" \
        : "=r"((r)[0]), "=r"((r)[1]), "=r"((r)[2]), "=r"((r)[3]) : "r"(addr))
// B operand: [K,N] k-row-major tile -> column fragments via TRANS ldmatrix
#define LDSM_X2_TRANS(r, addr) \
    asm volatile("ldmatrix.sync.aligned.m8n8.x2.trans.shared.b16 {%0,%1}, [%2];" \
        : "=r"((r)[0]), "=r"((r)[1]) : "r"(addr))
#define MMA_BF16(c, a, b) \
    asm volatile("mma.sync.aligned.m16n8k16.row.col.f32.bf16.bf16.f32 " \
        "{%0,%1,%2,%3},{%4,%5,%6,%7},{%8,%9},{%0,%1,%2,%3};" \
        : "+f"((c)[0]), "+f"((c)[1]), "+f"((c)[2]), "+f"((c)[3]) \
        : "r"((a)[0]), "r"((a)[1]), "r"((a)[2]), "r"((a)[3]), "r"((b)[0]), "r"((b)[1]))

// ---------------- edge dtype handling ----------------
__device__ __forceinline__ int edge_at(const int* p, int idx) {
    return g_is64 ? p[2 * idx] : p[idx];
}

__global__ void detect_kernel(const int* __restrict__ p) {
    __shared__ int red[256];
    int acc = 0;
    for (int i = threadIdx.x; i < 8192; i += 256) acc |= p[2 * i + 1];
    red[threadIdx.x] = acc;
    __syncthreads();
    for (int s = 128; s > 0; s >>= 1) {
        if (threadIdx.x < s) red[threadIdx.x] |= red[threadIdx.x + s];
        __syncthreads();
    }
    if (threadIdx.x == 0) g_is64 = (red[0] == 0) ? 1 : 0;
}

// ---------------- CSR build ----------------
__global__ void init_counts_kernel() {
    int i = blockIdx.x * blockDim.x + threadIdx.x;
    if (i < N_NODES) g_counts[i] = 1;
}
__global__ void count_kernel(const int* __restrict__ ei) {
    int i = blockIdx.x * blockDim.x + threadIdx.x;
    if (i < NE) atomicAdd(&g_counts[edge_at(ei, NE + i)], 1);
}
__global__ void __launch_bounds__(1024) scan_block_kernel() {
    __shared__ int sm[1024];
    int i = blockIdx.x * 1024 + threadIdx.x;
    int v = (i < N_NODES) ? g_counts[i] : 0;
    sm[threadIdx.x] = v;
    __syncthreads();
    for (int off = 1; off < 1024; off <<= 1) {
        int t = (threadIdx.x >= off) ? sm[threadIdx.x - off] : 0;
        __syncthreads();
        sm[threadIdx.x] += t;
        __syncthreads();
    }
    if (i < N_NODES) g_rowptr[i] = sm[threadIdx.x] - v;
    if (threadIdx.x == 1023) g_part[blockIdx.x] = sm[1023];
}
__global__ void scan_mid_kernel(int nblocks) {
    if (threadIdx.x == 0) {
        int run = 0;
        for (int b = 0; b < nblocks; b++) { int t = g_part[b]; g_part[b] = run; run += t; }
    }
}
__global__ void __launch_bounds__(1024) scan_add_kernel() {
    int i = blockIdx.x * 1024 + threadIdx.x;
    if (i < N_NODES) {
        int v = g_rowptr[i] + g_part[blockIdx.x];
        g_rowptr[i] = v;
        g_cursor[i] = v;
    }
    if (i == 0) g_rowptr[N_NODES] = E_TOT;
}
__global__ void fill_kernel(const int* __restrict__ ei) {
    int i = blockIdx.x * blockDim.x + threadIdx.x;
    if (i >= E_TOT) return;
    int src, dst;
    if (i < NE) { src = edge_at(ei, i); dst = edge_at(ei, NE + i); }
    else        { src = dst = i - NE; }
    int pos = atomicAdd(&g_cursor[dst], 1);
    g_src_sorted[pos] = src;
}

// ---------------- small-K GEMM (layer 1, K=18) ----------------
#define BM 128
#define BN 64
#define BK 16

__global__ void __launch_bounds__(256) gemm_small_kernel(const float* __restrict__ A,
                                                         const float* __restrict__ B,
                                                         float* __restrict__ C,
                                                         int M, int K, int Nc) {
    __shared__ float As[BK][BM + 4];
    __shared__ float Bs[BK][BN + 4];
    int tid = threadIdx.x;
    int bn0 = blockIdx.x * BN;
    int bm0 = blockIdx.y * BM;
    int tr = tid >> 4;
    int tc = tid & 15;
    int a_row = tid >> 1;
    int a_cb  = (tid & 1) * 8;
    int b_row = tid >> 4;
    int b_col = (tid & 15) * 4;

    float acc[8][4];
#pragma unroll
    for (int i = 0; i < 8; i++)
#pragma unroll
        for (int j = 0; j < 4; j++) acc[i][j] = 0.f;

    for (int k0 = 0; k0 < K; k0 += BK) {
        int gm = bm0 + a_row;
#pragma unroll
        for (int i = 0; i < 8; i++) {
            int gk = k0 + a_cb + i;
            As[a_cb + i][a_row] = (gm < M && gk < K) ? A[(long long)gm * K + gk] : 0.f;
        }
        {
            int gk = k0 + b_row;
            float4 bv = make_float4(0.f, 0.f, 0.f, 0.f);
            if (gk < K) bv = *(const float4*)&B[(long long)gk * Nc + bn0 + b_col];
            *(float4*)&Bs[b_row][b_col] = bv;
        }
        __syncthreads();
#pragma unroll
        for (int kk = 0; kk < BK; kk++) {
            float a[8], b[4];
#pragma unroll
            for (int i = 0; i < 8; i++) a[i] = As[kk][tr * 8 + i];
#pragma unroll
            for (int j = 0; j < 4; j++) b[j] = Bs[kk][tc * 4 + j];
#pragma unroll
            for (int i = 0; i < 8; i++)
#pragma unroll
                for (int j = 0; j < 4; j++) acc[i][j] += a[i] * b[j];
        }
        __syncthreads();
    }
#pragma unroll
    for (int i = 0; i < 8; i++) {
        int gm = bm0 + tr * 8 + i;
        if (gm < M) {
#pragma unroll
            for (int j = 0; j < 4; j++)
                C[(long long)gm * Nc + bn0 + tc * 4 + j] = acc[i][j];
        }
    }
}

// ---------------- W bf16 split (elementwise, native [K][N] layout kept) ----------------
__global__ void __launch_bounds__(256) wsplit_kernel(const float* __restrict__ W,
                                                     __nv_bfloat16* __restrict__ whi,
                                                     __nv_bfloat16* __restrict__ wlo) {
    int i = blockIdx.x * blockDim.x + threadIdx.x;
    if (i < HCDIM * HCDIM) {
        float v = W[i];
        __nv_bfloat16 hi = __float2bfloat16_rn(v);
        whi[i] = hi;
        wlo[i] = __float2bfloat16_rn(v - __bfloat162float(hi));
    }
}

// ---------------- mma.sync bf16-split GEMM: C[M,512] = X @ W, fused alpha epilogue ------
// Block tile 128x128, BK=32, 8 warps (wm 0..3 x wn 0..1), warp tile 32 rows x 64 cols.
// A warp's 64 columns == exactly one head -> per-row alpha dots computed from fragments.
#define KTILES  (HCDIM / 32)      // 16
#define APITCH  80                // 32 bf16 = 64 B + 16 B pad
#define BPITCH  272               // 128 bf16 = 256 B + 16 B pad
#define A_TB    (128 * APITCH)    // 10240
#define B_TB    (32 * BPITCH)     // 8704
#define BUF_B   (2 * A_TB + 2 * B_TB)   // 37888
#define GSMEM   (2 * BUF_B)       // 75776

__global__ void __launch_bounds__(256, 2)
mma_gemm_kernel(const __nv_bfloat16* __restrict__ Ahi,
                const __nv_bfloat16* __restrict__ Alo,
                const __nv_bfloat16* __restrict__ Whi,
                const __nv_bfloat16* __restrict__ Wlo,
                const float* __restrict__ a_src,
                const float* __restrict__ a_dst,
                float* __restrict__ C, int M) {
    extern __shared__ char smem[];
    uint32_t sb = smem_u32(smem);
    int tid = threadIdx.x, lane = tid & 31, wid = tid >> 5;
    int wm = wid & 3, wn = wid >> 2;            // 4 x 2 warps -> 128 rows x 128 cols
    int bm0 = blockIdx.y * 128, bn0 = blockIdx.x * 128;

    float acc[2][8][4];
#pragma unroll
    for (int im = 0; im < 2; im++)
#pragma unroll
        for (int in_ = 0; in_ < 8; in_++)
#pragma unroll
            for (int q = 0; q < 4; q++) acc[im][in_][q] = 0.f;

    auto load_tile = [&](int kt, int b) {
        uint32_t base = sb + (uint32_t)b * BUF_B;
        // A tiles: 128 rows x 64B (4 chunks of 16B) = 512 chunks per matrix
#pragma unroll
        for (int m = 0; m < 2; m++) {
            const __nv_bfloat16* srcm = m ? Alo : Ahi;
            uint32_t tb = base + (uint32_t)m * A_TB;
#pragma unroll
            for (int q = 0; q < 2; q++) {
                int idx = q * 256 + tid;
                int r = idx >> 2, ch = idx & 3;
                int gr = bm0 + r;
                int sz = 16;
                if (gr >= M) { gr = 0; sz = 0; }
                cp_async16(tb + (uint32_t)(r * APITCH + ch * 16),
                           srcm + (size_t)gr * HCDIM + kt * 32 + ch * 8, sz);
            }
        }
        // B tiles: 32 k-rows x 256B (16 chunks of 16B) = 512 chunks per matrix
#pragma unroll
        for (int m = 0; m < 2; m++) {
            const __nv_bfloat16* srcm = m ? Wlo : Whi;
            uint32_t tb = base + 2 * A_TB + (uint32_t)m * B_TB;
#pragma unroll
            for (int q = 0; q < 2; q++) {
                int idx = q * 256 + tid;
                int r = idx >> 4, ch = idx & 15;
                cp_async16(tb + (uint32_t)(r * BPITCH + ch * 16),
                           srcm + (size_t)(kt * 32 + r) * HCDIM + bn0 + ch * 8, 16);
            }
        }
        cp_commit();
    };

    load_tile(0, 0);

    for (int t = 0; t < KTILES; t++) {
        int b = t & 1;
        if (t + 1 < KTILES) { load_tile(t + 1, b ^ 1); cp_wait1(); }
        else cp_wait0();
        __syncthreads();

        uint32_t abase = sb + (uint32_t)b * BUF_B;
        uint32_t bbase = abase + 2 * A_TB;
#pragma unroll
        for (int ks = 0; ks < 2; ks++) {
            uint32_t ah[2][4], al[2][4];
#pragma unroll
            for (int im = 0; im < 2; im++) {
                uint32_t ra = abase
                    + (uint32_t)((wm * 32 + im * 16 + (lane & 15)) * APITCH
                                 + (ks * 16 + (lane >> 4) * 8) * 2);
                LDSM_X4(ah[im], ra);
                LDSM_X4(al[im], ra + A_TB);
            }
#pragma unroll
            for (int in_ = 0; in_ < 8; in_++) {
                uint32_t rb = bbase
                    + (uint32_t)((ks * 16 + (lane & 15)) * BPITCH
                                 + (wn * 64 + in_ * 8) * 2);
                uint32_t bh[2], bl[2];
                LDSM_X2_TRANS(bh, rb);
                LDSM_X2_TRANS(bl, rb + B_TB);
#pragma unroll
                for (int im = 0; im < 2; im++) {
                    MMA_BF16(acc[im][in_], ah[im], bh);
                    MMA_BF16(acc[im][in_], ah[im], bl);
                    MMA_BF16(acc[im][in_], al[im], bh);
                }
            }
        }
        __syncthreads();
    }

    // ---- C store: frag rows lane/4 (+8), cols (lane%3)*2 within in_*8 block ----
#pragma unroll
    for (int im = 0; im < 2; im++) {
        int r0 = bm0 + wm * 32 + im * 16 + (lane >> 2);
#pragma unroll
        for (int in_ = 0; in_ < 8; in_++) {
            int col = bn0 + wn * 64 + in_ * 8 + (lane & 3) * 2;
            if (r0 < M)
                *(float2*)&C[(size_t)r0 * HCDIM + col] =
                    make_float2(acc[im][in_][0], acc[im][in_][1]);
            if (r0 + 8 < M)
                *(float2*)&C[(size_t)(r0 + 8) * HCDIM + col] =
                    make_float2(acc[im][in_][2], acc[im][in_][3]);
        }
    }

    // ---- fused alpha: warp's 64 cols = one head ----
    {
        int hh = (bn0 >> 6) + wn;
        float pas[4] = {0.f, 0.f, 0.f, 0.f};
        float pad_[4] = {0.f, 0.f, 0.f, 0.f};
#pragma unroll
        for (int in_ = 0; in_ < 8; in_++) {
            int c0 = in_ * 8 + (lane & 3) * 2;
            float s0 = __ldg(&a_src[hh * CDIM + c0]);
            float s1 = __ldg(&a_src[hh * CDIM + c0 + 1]);
            float d0 = __ldg(&a_dst[hh * CDIM + c0]);
            float d1 = __ldg(&a_dst[hh * CDIM + c0 + 1]);
#pragma unroll
            for (int im = 0; im < 2; im++) {
                pas[im * 2]     += acc[im][in_][0] * s0 + acc[im][in_][1] * s1;
                pas[im * 2 + 1] += acc[im][in_][2] * s0 + acc[im][in_][3] * s1;
                pad_[im * 2]     += acc[im][in_][0] * d0 + acc[im][in_][1] * d1;
                pad_[im * 2 + 1] += acc[im][in_][2] * d0 + acc[im][in_][3] * d1;
            }
        }
#pragma unroll
        for (int k = 0; k < 4; k++) {
            pas[k]  += __shfl_xor_sync(0xffffffffu, pas[k], 1);
            pas[k]  += __shfl_xor_sync(0xffffffffu, pas[k], 2);
            pad_[k] += __shfl_xor_sync(0xffffffffu, pad_[k], 1);
            pad_[k] += __shfl_xor_sync(0xffffffffu, pad_[k], 2);
        }
        if ((lane & 3) == 0) {
#pragma unroll
            for (int im = 0; im < 2; im++) {
                int r0 = bm0 + wm * 32 + im * 16 + (lane >> 2);
                if (r0 < M) {
                    g_as[r0 * NHEADS + hh] = pas[im * 2];
                    g_ad[r0 * NHEADS + hh] = pad_[im * 2];
                }
                if (r0 + 8 < M) {
                    g_as[(r0 + 8) * NHEADS + hh] = pas[im * 2 + 1];
                    g_ad[(r0 + 8) * NHEADS + hh] = pad_[im * 2 + 1];
                }
            }
        }
    }
}

// ---------------- alpha_s / alpha_d (layer 1 only) ----------------
__global__ void alpha_kernel(const float* __restrict__ h,
                             const float* __restrict__ a_src,
                             const float* __restrict__ a_dst) {
    int wid = (blockIdx.x * blockDim.x + threadIdx.x) >> 5;
    int lane = threadIdx.x & 31;
    if (wid >= N_NODES * NHEADS) return;
    int n = wid >> 3, hh = wid & 7;
    const float* hp = h + (long long)n * HCDIM + hh * CDIM;
    float v1 = hp[lane], v2 = hp[lane + 32];
    float s1 = a_src[hh * CDIM + lane], s2 = a_src[hh * CDIM + lane + 32];
    float d1 = a_dst[hh * CDIM + lane], d2 = a_dst[hh * CDIM + lane + 32];
    float as = v1 * s1 + v2 * s2;
    float ad = v1 * d1 + v2 * d2;
#pragma unroll
    for (int off = 16; off > 0; off >>= 1) {
        as += __shfl_xor_sync(0xffffffffu, as, off);
        ad += __shfl_xor_sync(0xffffffffu, ad, off);
    }
    if (lane == 0) {
        g_as[n * NHEADS + hh] = as;
        g_ad[n * NHEADS + hh] = ad;
    }
}

// ---------------- segment softmax ----------------
__global__ void stats_kernel() {
    int lane = threadIdx.x & 31;
    int warp = (blockIdx.x * blockDim.x + threadIdx.x) >> 5;
    int sub = lane >> 3, hh = lane & 7;
    int n = warp * 4 + sub;
    if (n >= N_NODES) return;
    int row = g_rowptr[n], end = g_rowptr[n + 1];
    float ad = g_ad[n * NHEADS + hh];
    float m = -INFINITY, s = 0.f;
    for (int j = row; j < end; j++) {
        int src = g_src_sorted[j];
        float e = g_as[src * NHEADS + hh] + ad;
        e = (e > 0.f) ? e : NEG_SLOPE * e;
        g_alpha[(size_t)j * NHEADS + hh] = e;
        float nm = fmaxf(m, e);
        s = s * __expf(m - nm) + __expf(e - nm);
        m = nm;
    }
    float inv = 1.0f / (s + 1e-16f);
    for (int j = row; j < end; j++) {
        float e = g_alpha[(size_t)j * NHEADS + hh];
        g_alpha[(size_t)j * NHEADS + hh] = __expf(e - m) * inv;
    }
}

// ---------------- heavy aggregation ----------------
__device__ __forceinline__ uint32_t pack_bf2(float a, float b) {
    __nv_bfloat162 t;
    t.x = __float2bfloat16_rn(a);
    t.y = __float2bfloat16_rn(b);
    return *(uint32_t*)&t;
}

__global__ void __launch_bounds__(128) aggregate_kernel(const float* __restrict__ hin,
                                                        const float* __restrict__ bias,
                                                        __nv_bfloat16* __restrict__ xhi,
                                                        __nv_bfloat16* __restrict__ xlo,
                                                        float* __restrict__ outp,
                                                        int mode) {
    __shared__ float4 sm4[HCDIM / 4];
    int n = blockIdx.x;
    int tid = threadIdx.x;
    int head = tid >> 4;
    int row = g_rowptr[n], end = g_rowptr[n + 1];
    const float4* h4 = (const float4*)hin;
    float4 acc = make_float4(0.f, 0.f, 0.f, 0.f);
    int j = row;
    for (; j + 1 < end; j += 2) {
        int s0 = __ldg(&g_src_sorted[j]);
        int s1 = __ldg(&g_src_sorted[j + 1]);
        float a0 = __ldg(&g_alpha[(size_t)j * NHEADS + head]);
        float a1 = __ldg(&g_alpha[(size_t)(j + 1) * NHEADS + head]);
        float4 v0 = __ldg(&h4[(long long)s0 * (HCDIM / 4) + tid]);
        float4 v1 = __ldg(&h4[(long long)s1 * (HCDIM / 4) + tid]);
        acc.x = fmaf(a0, v0.x, fmaf(a1, v1.x, acc.x));
        acc.y = fmaf(a0, v0.y, fmaf(a1, v1.y, acc.y));
        acc.z = fmaf(a0, v0.z, fmaf(a1, v1.z, acc.z));
        acc.w = fmaf(a0, v0.w, fmaf(a1, v1.w, acc.w));
    }
    if (j < end) {
        int s0 = __ldg(&g_src_sorted[j]);
        float a0 = __ldg(&g_alpha[(size_t)j * NHEADS + head]);
        float4 v0 = __ldg(&h4[(long long)s0 * (HCDIM / 4) + tid]);
        acc.x = fmaf(a0, v0.x, acc.x);
        acc.y = fmaf(a0, v0.y, acc.y);
        acc.z = fmaf(a0, v0.z, acc.z);
        acc.w = fmaf(a0, v0.w, acc.w);
    }
    if (mode == 0) {
        float4 b4 = ((const float4*)bias)[tid];
        float vx = acc.x + b4.x; vx = (vx > 0.f) ? vx : expm1f(vx);
        float vy = acc.y + b4.y; vy = (vy > 0.f) ? vy : expm1f(vy);
        float vz = acc.z + b4.z; vz = (vz > 0.f) ? vz : expm1f(vz);
        float vw = acc.w + b4.w; vw = (vw > 0.f) ? vw : expm1f(vw);
        __nv_bfloat16 hx = __float2bfloat16_rn(vx), hy = __float2bfloat16_rn(vy);
        __nv_bfloat16 hz = __float2bfloat16_rn(vz), hw = __float2bfloat16_rn(vw);
        float lx = vx - __bfloat162float(hx), ly = vy - __bfloat162float(hy);
        float lz = vz - __bfloat162float(hz), lw = vw - __bfloat162float(hw);
        size_t base = ((size_t)n * HCDIM + tid * 4) >> 1;   // uint32 index
        uint32_t* hip = (uint32_t*)xhi;
        uint32_t* lop = (uint32_t*)xlo;
        __nv_bfloat162 h01; h01.x = hx; h01.y = hy;
        __nv_bfloat162 h23; h23.x = hz; h23.y = hw;
        hip[base]     = *(uint32_t*)&h01;
        hip[base + 1] = *(uint32_t*)&h23;
        lop[base]     = pack_bf2(lx, ly);
        lop[base + 1] = pack_bf2(lz, lw);
    } else {
        sm4[tid] = acc;
        __syncthreads();
        if (tid < 16) {
            float4 s = make_float4(0.f, 0.f, 0.f, 0.f);
#pragma unroll
            for (int hh = 0; hh < NHEADS; hh++) {
                float4 f = sm4[hh * 16 + tid];
                s.x += f.x; s.y += f.y; s.z += f.z; s.w += f.w;
            }
            float4 b4 = ((const float4*)bias)[tid];
            float4 o;
            o.x = s.x * (1.0f / NHEADS) + b4.x;
            o.y = s.y * (1.0f / NHEADS) + b4.y;
            o.z = s.z * (1.0f / NHEADS) + b4.z;
            o.w = s.w * (1.0f / NHEADS) + b4.w;
            ((float4*)outp)[(long long)n * (CDIM / 4) + tid] = o;
        }
    }
}

// ---------------- final projection ----------------
__global__ void __launch_bounds__(256) proj_kernel(const float* __restrict__ x3,
                                                   const float* __restrict__ Wout,
                                                   const float* __restrict__ bout,
                                                   float* __restrict__ out) {
    __shared__ float Ws[CDIM * 16];
    __shared__ float bs[16];
    int tid = threadIdx.x;
    for (int idx = tid; idx < CDIM * 16; idx += 256) {
        int c = idx >> 4, o = idx & 15;
        Ws[idx] = (o < OUT_DIM) ? Wout[c * OUT_DIM + o] : 0.f;
    }
    if (tid < 16) bs[tid] = (tid < OUT_DIM) ? bout[tid] : 0.f;
    __syncthreads();
    int tx = tid & 15;
    int tn = tid >> 4;
    int n = blockIdx.x * 16 + tn;
    if (n >= N_NODES) return;
    const float* xr = x3 + (long long)n * CDIM;
    float acc = 0.f;
#pragma unroll
    for (int c = 0; c < CDIM; c++) acc += xr[c] * Ws[c * 16 + tx];
    if (tx < OUT_DIM) out[(long long)n * OUT_DIM + tx] = acc + bs[tx];
}

// ---------------- launch ----------------
extern "C" void kernel_launch(void* const* d_in, const int* in_sizes, int n_in,
                              void* d_out, int out_size) {
    const float* x    = (const float*)d_in[0];
    const int*   ei   = (const int*)d_in[1];
    const float* W1   = (const float*)d_in[2];
    const float* a1s  = (const float*)d_in[3];
    const float* a1d  = (const float*)d_in[4];
    const float* b1   = (const float*)d_in[5];
    const float* W2   = (const float*)d_in[6];
    const float* a2s  = (const float*)d_in[7];
    const float* a2d  = (const float*)d_in[8];
    const float* b2   = (const float*)d_in[9];
    const float* W3   = (const float*)d_in[10];
    const float* a3s  = (const float*)d_in[11];
    const float* a3d  = (const float*)d_in[12];
    const float* b3   = (const float*)d_in[13];
    const float* Wout = (const float*)d_in[14];
    const float* bout = (const float*)d_in[15];
    float* out = (float*)d_out;

    float *p_h, *p_x3;
    __nv_bfloat16 *p_xhi, *p_xlo, *p_w2hi, *p_w2lo, *p_w3hi, *p_w3lo;
    cudaGetSymbolAddress((void**)&p_h,    g_h);
    cudaGetSymbolAddress((void**)&p_x3,   g_x3);
    cudaGetSymbolAddress((void**)&p_xhi,  g_xhi);
    cudaGetSymbolAddress((void**)&p_xlo,  g_xlo);
    cudaGetSymbolAddress((void**)&p_w2hi, g_w2hi);
    cudaGetSymbolAddress((void**)&p_w2lo, g_w2lo);
    cudaGetSymbolAddress((void**)&p_w3hi, g_w3hi);
    cudaGetSymbolAddress((void**)&p_w3lo, g_w3lo);

    cudaFuncSetAttribute(mma_gemm_kernel, cudaFuncAttributeMaxDynamicSharedMemorySize, GSMEM);

    const int scan_blocks = (N_NODES + 1023) / 1024;

    detect_kernel<<<1, 256>>>(ei);
    init_counts_kernel<<<(N_NODES + 255) / 256, 256>>>();
    count_kernel<<<(NE + 255) / 256, 256>>>(ei);
    scan_block_kernel<<<scan_blocks, 1024>>>();
    scan_mid_kernel<<<1, 32>>>(scan_blocks);
    scan_add_kernel<<<scan_blocks, 1024>>>();
    fill_kernel<<<(E_TOT + 255) / 256, 256>>>(ei);

    // W2/W3 bf16 split (elementwise, layout preserved)
    int wsplit_blocks = (HCDIM * HCDIM + 255) / 256;
    wsplit_kernel<<<wsplit_blocks, 256>>>(W2, p_w2hi, p_w2lo);
    wsplit_kernel<<<wsplit_blocks, 256>>>(W3, p_w3hi, p_w3lo);

    dim3 sgrid(HCDIM / BN, (N_NODES + BM - 1) / BM);
    dim3 mgrid(HCDIM / 128, (N_NODES + 127) / 128);
    int alpha_blocks = (N_NODES * NHEADS + 7) / 8;
    int stats_blocks = (N_NODES + 31) / 32;

    // ---- layer 1 ----
    gemm_small_kernel<<<sgrid, 256>>>(x, W1, p_h, N_NODES, F_IN, HCDIM);
    alpha_kernel<<<alpha_blocks, 256>>>(p_h, a1s, a1d);
    stats_kernel<<<stats_blocks, 256>>>();
    aggregate_kernel<<<N_NODES, 128>>>(p_h, b1, p_xhi, p_xlo, nullptr, 0);

    // ---- layer 2 (mma.sync bf16-split GEMM, fused alpha) ----
    mma_gemm_kernel<<<mgrid, 256, GSMEM>>>(p_xhi, p_xlo, p_w2hi, p_w2lo, a2s, a2d, p_h, N_NODES);
    stats_kernel<<<stats_blocks, 256>>>();
    aggregate_kernel<<<N_NODES, 128>>>(p_h, b2, p_xhi, p_xlo, nullptr, 0);

    // ---- layer 3 ----
    mma_gemm_kernel<<<mgrid, 256, GSMEM>>>(p_xhi, p_xlo, p_w3hi, p_w3lo, a3s, a3d, p_h, N_NODES);
    stats_kernel<<<stats_blocks, 256>>>();
    aggregate_kernel<<<N_NODES, 128>>>(p_h, b3, nullptr, nullptr, p_x3, 1);

    // ---- output projection ----
    proj_kernel<<<(N_NODES + 15) / 16, 256>>>(p_x3, Wout, bout, out);
}

// round 9
// speedup vs baseline: 3.2287x; 1.0419x over previous
#include <cuda_runtime.h>
#include <cuda_bf16.h>
#include <cstdint>
#include <stdint.h>
#include <math.h>

#define N_NODES 50000
#define F_IN    18
#define NHEADS  8
#define CDIM    64
#define HCDIM   512
#define NE      400000
#define E_TOT   (NE + N_NODES)
#define OUT_DIM 15
#define NEG_SLOPE 0.2f

// ---------------- scratch (static device globals; no runtime allocation) ----------------
__device__ float g_h [N_NODES * HCDIM];
__device__ float g_x3[N_NODES * CDIM];
__device__ __nv_bfloat16 g_xhi[N_NODES * HCDIM];
__device__ __nv_bfloat16 g_xlo[N_NODES * HCDIM];
__device__ __nv_bfloat16 g_w2hi[HCDIM * HCDIM];
__device__ __nv_bfloat16 g_w2lo[HCDIM * HCDIM];
__device__ __nv_bfloat16 g_w3hi[HCDIM * HCDIM];
__device__ __nv_bfloat16 g_w3lo[HCDIM * HCDIM];
__device__ float g_as[N_NODES * NHEADS];
__device__ float g_ad[N_NODES * NHEADS];
__device__ float g_C [N_NODES * NHEADS];          // softmax constant: m + log(s+eps)
__device__ float g_alpha[(size_t)E_TOT * NHEADS]; // stores raw e (LeakyReLU'd logits)
__device__ int   g_src_sorted[E_TOT];
__device__ int   g_rowptr[N_NODES + 1];
__device__ int   g_cursor[N_NODES];
__device__ int   g_counts[N_NODES];
__device__ int   g_part[64];
__device__ int   g_is64;

// ---------------- PTX helpers (portable: sm_80-era features only) ----------------
__device__ __forceinline__ uint32_t smem_u32(const void* p) {
    uint32_t a;
    asm("{ .reg .u64 t; cvta.to.shared.u64 t, %1; cvt.u32.u64 %0, t; }" : "=r"(a) : "l"(p));
    return a;
}
static __device__ __forceinline__ void cp_async16(uint32_t dst, const void* src, int sz) {
    asm volatile("cp.async.cg.shared.global [%0], [%1], 16, %2;\n"
                 :: "r"(dst), "l"(src), "r"(sz) : "memory");
}
static __device__ __forceinline__ void cp_commit() {
    asm volatile("cp.async.commit_group;" ::: "memory");
}
static __device__ __forceinline__ void cp_wait0() {
    asm volatile("cp.async.wait_group 0;" ::: "memory");
}
static __device__ __forceinline__ void cp_wait1() {
    asm volatile("cp.async.wait_group 1;" ::: "memory");
}

#define LDSM_X4(r, addr) \
    asm volatile("ldmatrix.sync.aligned.m8n8.x4.shared.b16 {%0,%1,%2,%3}, [%4];" \
        : "=r"((r)[0]), "=r"((r)[1]), "=r"((r)[2]), "=r"((r)[3]) : "r"(addr))
// B operand: [K,N] k-row-major tile -> column fragments for TWO 8-col blocks at once
#define LDSM_X4_TRANS(r, addr) \
    asm volatile("ldmatrix.sync.aligned.m8n8.x4.trans.shared.b16 {%0,%1,%2,%3}, [%4];" \
        : "=r"((r)[0]), "=r"((r)[1]), "=r"((r)[2]), "=r"((r)[3]) : "r"(addr))
#define MMA_BF16(c, a, b) \
    asm volatile("mma.sync.aligned.m16n8k16.row.col.f32.bf16.bf16.f32 " \
        "{%0,%1,%2,%3},{%4,%5,%6,%7},{%8,%9},{%0,%1,%2,%3};" \
        : "+f"((c)[0]), "+f"((c)[1]), "+f"((c)[2]), "+f"((c)[3]) \
        : "r"((a)[0]), "r"((a)[1]), "r"((a)[2]), "r"((a)[3]), "r"((b)[0]), "r"((b)[1]))

// ---------------- edge dtype handling ----------------
__device__ __forceinline__ int edge_at(const int* p, int idx) {
    return g_is64 ? p[2 * idx] : p[idx];
}

__global__ void detect_kernel(const int* __restrict__ p) {
    __shared__ int red[256];
    int acc = 0;
    for (int i = threadIdx.x; i < 8192; i += 256) acc |= p[2 * i + 1];
    red[threadIdx.x] = acc;
    __syncthreads();
    for (int s = 128; s > 0; s >>= 1) {
        if (threadIdx.x < s) red[threadIdx.x] |= red[threadIdx.x + s];
        __syncthreads();
    }
    if (threadIdx.x == 0) g_is64 = (red[0] == 0) ? 1 : 0;
}

// ---------------- CSR build ----------------
__global__ void init_counts_kernel() {
    int i = blockIdx.x * blockDim.x + threadIdx.x;
    if (i < N_NODES) g_counts[i] = 1;
}
__global__ void count_kernel(const int* __restrict__ ei) {
    int i = blockIdx.x * blockDim.x + threadIdx.x;
    if (i < NE) atomicAdd(&g_counts[edge_at(ei, NE + i)], 1);
}
__global__ void __launch_bounds__(1024) scan_block_kernel() {
    __shared__ int sm[1024];
    int i = blockIdx.x * 1024 + threadIdx.x;
    int v = (i < N_NODES) ? g_counts[i] : 0;
    sm[threadIdx.x] = v;
    __syncthreads();
    for (int off = 1; off < 1024; off <<= 1) {
        int t = (threadIdx.x >= off) ? sm[threadIdx.x - off] : 0;
        __syncthreads();
        sm[threadIdx.x] += t;
        __syncthreads();
    }
    if (i < N_NODES) g_rowptr[i] = sm[threadIdx.x] - v;
    if (threadIdx.x == 1023) g_part[blockIdx.x] = sm[1023];
}
__global__ void scan_mid_kernel(int nblocks) {
    if (threadIdx.x == 0) {
        int run = 0;
        for (int b = 0; b < nblocks; b++) { int t = g_part[b]; g_part[b] = run; run += t; }
    }
}
__global__ void __launch_bounds__(1024) scan_add_kernel() {
    int i = blockIdx.x * 1024 + threadIdx.x;
    if (i < N_NODES) {
        int v = g_rowptr[i] + g_part[blockIdx.x];
        g_rowptr[i] = v;
        g_cursor[i] = v;
    }
    if (i == 0) g_rowptr[N_NODES] = E_TOT;
}
__global__ void fill_kernel(const int* __restrict__ ei) {
    int i = blockIdx.x * blockDim.x + threadIdx.x;
    if (i >= E_TOT) return;
    int src, dst;
    if (i < NE) { src = edge_at(ei, i); dst = edge_at(ei, NE + i); }
    else        { src = dst = i - NE; }
    int pos = atomicAdd(&g_cursor[dst], 1);
    g_src_sorted[pos] = src;
}

// ---------------- small-K GEMM (layer 1, K=18) with fused alpha epilogue ----------------
// BN=64 => a block's column tile is exactly one head (blockIdx.x).
#define BM 128
#define BN 64
#define BK 16

__global__ void __launch_bounds__(256) gemm_small_kernel(const float* __restrict__ A,
                                                         const float* __restrict__ B,
                                                         const float* __restrict__ a_src,
                                                         const float* __restrict__ a_dst,
                                                         float* __restrict__ C,
                                                         int M, int K, int Nc) {
    __shared__ float As[BK][BM + 4];
    __shared__ float Bs[BK][BN + 4];
    int tid = threadIdx.x;
    int bn0 = blockIdx.x * BN;
    int bm0 = blockIdx.y * BM;
    int tr = tid >> 4;
    int tc = tid & 15;
    int a_row = tid >> 1;
    int a_cb  = (tid & 1) * 8;
    int b_row = tid >> 4;
    int b_col = (tid & 15) * 4;

    float acc[8][4];
#pragma unroll
    for (int i = 0; i < 8; i++)
#pragma unroll
        for (int j = 0; j < 4; j++) acc[i][j] = 0.f;

    for (int k0 = 0; k0 < K; k0 += BK) {
        int gm = bm0 + a_row;
#pragma unroll
        for (int i = 0; i < 8; i++) {
            int gk = k0 + a_cb + i;
            As[a_cb + i][a_row] = (gm < M && gk < K) ? A[(long long)gm * K + gk] : 0.f;
        }
        {
            int gk = k0 + b_row;
            float4 bv = make_float4(0.f, 0.f, 0.f, 0.f);
            if (gk < K) bv = *(const float4*)&B[(long long)gk * Nc + bn0 + b_col];
            *(float4*)&Bs[b_row][b_col] = bv;
        }
        __syncthreads();
#pragma unroll
        for (int kk = 0; kk < BK; kk++) {
            float a[8], b[4];
#pragma unroll
            for (int i = 0; i < 8; i++) a[i] = As[kk][tr * 8 + i];
#pragma unroll
            for (int j = 0; j < 4; j++) b[j] = Bs[kk][tc * 4 + j];
#pragma unroll
            for (int i = 0; i < 8; i++)
#pragma unroll
                for (int j = 0; j < 4; j++) acc[i][j] += a[i] * b[j];
        }
        __syncthreads();
    }
#pragma unroll
    for (int i = 0; i < 8; i++) {
        int gm = bm0 + tr * 8 + i;
        if (gm < M) {
#pragma unroll
            for (int j = 0; j < 4; j++)
                C[(long long)gm * Nc + bn0 + tc * 4 + j] = acc[i][j];
        }
    }

    // fused alpha for this head: dots over the 64 columns, reduce over the 16 tc lanes
    {
        int hh = blockIdx.x;
        float pas[8], pad_[8];
#pragma unroll
        for (int i = 0; i < 8; i++) { pas[i] = 0.f; pad_[i] = 0.f; }
#pragma unroll
        for (int j = 0; j < 4; j++) {
            float sj = __ldg(&a_src[hh * CDIM + tc * 4 + j]);
            float dj = __ldg(&a_dst[hh * CDIM + tc * 4 + j]);
#pragma unroll
            for (int i = 0; i < 8; i++) {
                pas[i]  = fmaf(acc[i][j], sj, pas[i]);
                pad_[i] = fmaf(acc[i][j], dj, pad_[i]);
            }
        }
#pragma unroll
        for (int off = 1; off < 16; off <<= 1) {
#pragma unroll
            for (int i = 0; i < 8; i++) {
                pas[i]  += __shfl_xor_sync(0xffffffffu, pas[i], off);
                pad_[i] += __shfl_xor_sync(0xffffffffu, pad_[i], off);
            }
        }
        if (tc == 0) {
#pragma unroll
            for (int i = 0; i < 8; i++) {
                int gm = bm0 + tr * 8 + i;
                if (gm < M) {
                    g_as[gm * NHEADS + hh] = pas[i];
                    g_ad[gm * NHEADS + hh] = pad_[i];
                }
            }
        }
    }
}

// ---------------- W bf16 split (elementwise, native [K][N] layout kept) ----------------
__global__ void __launch_bounds__(256) wsplit_kernel(const float* __restrict__ W,
                                                     __nv_bfloat16* __restrict__ whi,
                                                     __nv_bfloat16* __restrict__ wlo) {
    int i = blockIdx.x * blockDim.x + threadIdx.x;
    if (i < HCDIM * HCDIM) {
        float v = W[i];
        __nv_bfloat16 hi = __float2bfloat16_rn(v);
        whi[i] = hi;
        wlo[i] = __float2bfloat16_rn(v - __bfloat162float(hi));
    }
}

// ---------------- mma.sync bf16-split GEMM + fused alpha epilogue ----------------
#define KTILES  (HCDIM / 32)      // 16
#define APITCH  80
#define BPITCH  272
#define A_TB    (128 * APITCH)
#define B_TB    (32 * BPITCH)
#define BUF_B   (2 * A_TB + 2 * B_TB)
#define GSMEM   (2 * BUF_B)

__global__ void __launch_bounds__(256, 2)
mma_gemm_kernel(const __nv_bfloat16* __restrict__ Ahi,
                const __nv_bfloat16* __restrict__ Alo,
                const __nv_bfloat16* __restrict__ Whi,
                const __nv_bfloat16* __restrict__ Wlo,
                const float* __restrict__ a_src,
                const float* __restrict__ a_dst,
                float* __restrict__ C, int M) {
    extern __shared__ char smem[];
    uint32_t sb = smem_u32(smem);
    int tid = threadIdx.x, lane = tid & 31, wid = tid >> 5;
    int wm = wid & 3, wn = wid >> 2;
    int bm0 = blockIdx.y * 128, bn0 = blockIdx.x * 128;

    float acc[2][8][4];
#pragma unroll
    for (int im = 0; im < 2; im++)
#pragma unroll
        for (int in_ = 0; in_ < 8; in_++)
#pragma unroll
            for (int q = 0; q < 4; q++) acc[im][in_][q] = 0.f;

    auto load_tile = [&](int kt, int b) {
        uint32_t base = sb + (uint32_t)b * BUF_B;
#pragma unroll
        for (int m = 0; m < 2; m++) {
            const __nv_bfloat16* srcm = m ? Alo : Ahi;
            uint32_t tb = base + (uint32_t)m * A_TB;
#pragma unroll
            for (int q = 0; q < 2; q++) {
                int idx = q * 256 + tid;
                int r = idx >> 2, ch = idx & 3;
                int gr = bm0 + r;
                int sz = 16;
                if (gr >= M) { gr = 0; sz = 0; }
                cp_async16(tb + (uint32_t)(r * APITCH + ch * 16),
                           srcm + (size_t)gr * HCDIM + kt * 32 + ch * 8, sz);
            }
        }
#pragma unroll
        for (int m = 0; m < 2; m++) {
            const __nv_bfloat16* srcm = m ? Wlo : Whi;
            uint32_t tb = base + 2 * A_TB + (uint32_t)m * B_TB;
#pragma unroll
            for (int q = 0; q < 2; q++) {
                int idx = q * 256 + tid;
                int r = idx >> 4, ch = idx & 15;
                cp_async16(tb + (uint32_t)(r * BPITCH + ch * 16),
                           srcm + (size_t)(kt * 32 + r) * HCDIM + bn0 + ch * 8, 16);
            }
        }
        cp_commit();
    };

    load_tile(0, 0);

    for (int t = 0; t < KTILES; t++) {
        int b = t & 1;
        if (t + 1 < KTILES) { load_tile(t + 1, b ^ 1); cp_wait1(); }
        else cp_wait0();
        __syncthreads();

        uint32_t abase = sb + (uint32_t)b * BUF_B;
        uint32_t bbase = abase + 2 * A_TB;
#pragma unroll
        for (int ks = 0; ks < 2; ks++) {
            uint32_t ah[2][4], al[2][4];
#pragma unroll
            for (int im = 0; im < 2; im++) {
                uint32_t ra = abase
                    + (uint32_t)((wm * 32 + im * 16 + (lane & 15)) * APITCH
                                 + (ks * 16 + (lane >> 4) * 8) * 2);
                LDSM_X4(ah[im], ra);
                LDSM_X4(al[im], ra + A_TB);
            }
            // B: x4.trans covers two 8-col blocks per instruction
            int g = lane >> 3;
#pragma unroll
            for (int in2 = 0; in2 < 4; in2++) {
                uint32_t rb = bbase
                    + (uint32_t)((ks * 16 + (lane & 7) + (g & 1) * 8) * BPITCH
                                 + (wn * 64 + in2 * 16 + (g >> 1) * 8) * 2);
                uint32_t bh[4], bl[4];
                LDSM_X4_TRANS(bh, rb);
                LDSM_X4_TRANS(bl, rb + B_TB);
#pragma unroll
                for (int im = 0; im < 2; im++) {
                    MMA_BF16(acc[im][in2 * 2],     ah[im], (bh + 0));
                    MMA_BF16(acc[im][in2 * 2],     ah[im], (bl + 0));
                    MMA_BF16(acc[im][in2 * 2],     al[im], (bh + 0));
                    MMA_BF16(acc[im][in2 * 2 + 1], ah[im], (bh + 2));
                    MMA_BF16(acc[im][in2 * 2 + 1], ah[im], (bl + 2));
                    MMA_BF16(acc[im][in2 * 2 + 1], al[im], (bh + 2));
                }
            }
        }
        __syncthreads();
    }

    // ---- C store ----
#pragma unroll
    for (int im = 0; im < 2; im++) {
        int r0 = bm0 + wm * 32 + im * 16 + (lane >> 2);
#pragma unroll
        for (int in_ = 0; in_ < 8; in_++) {
            int col = bn0 + wn * 64 + in_ * 8 + (lane & 3) * 2;
            if (r0 < M)
                *(float2*)&C[(size_t)r0 * HCDIM + col] =
                    make_float2(acc[im][in_][0], acc[im][in_][1]);
            if (r0 + 8 < M)
                *(float2*)&C[(size_t)(r0 + 8) * HCDIM + col] =
                    make_float2(acc[im][in_][2], acc[im][in_][3]);
        }
    }

    // ---- fused alpha: warp's 64 cols = one head ----
    {
        int hh = (bn0 >> 6) + wn;
        float pas[4] = {0.f, 0.f, 0.f, 0.f};
        float pad_[4] = {0.f, 0.f, 0.f, 0.f};
#pragma unroll
        for (int in_ = 0; in_ < 8; in_++) {
            int c0 = in_ * 8 + (lane & 3) * 2;
            float s0 = __ldg(&a_src[hh * CDIM + c0]);
            float s1 = __ldg(&a_src[hh * CDIM + c0 + 1]);
            float d0 = __ldg(&a_dst[hh * CDIM + c0]);
            float d1 = __ldg(&a_dst[hh * CDIM + c0 + 1]);
#pragma unroll
            for (int im = 0; im < 2; im++) {
                pas[im * 2]     += acc[im][in_][0] * s0 + acc[im][in_][1] * s1;
                pas[im * 2 + 1] += acc[im][in_][2] * s0 + acc[im][in_][3] * s1;
                pad_[im * 2]     += acc[im][in_][0] * d0 + acc[im][in_][1] * d1;
                pad_[im * 2 + 1] += acc[im][in_][2] * d0 + acc[im][in_][3] * d1;
            }
        }
#pragma unroll
        for (int k = 0; k < 4; k++) {
            pas[k]  += __shfl_xor_sync(0xffffffffu, pas[k], 1);
            pas[k]  += __shfl_xor_sync(0xffffffffu, pas[k], 2);
            pad_[k] += __shfl_xor_sync(0xffffffffu, pad_[k], 1);
            pad_[k] += __shfl_xor_sync(0xffffffffu, pad_[k], 2);
        }
        if ((lane & 3) == 0) {
#pragma unroll
            for (int im = 0; im < 2; im++) {
                int r0 = bm0 + wm * 32 + im * 16 + (lane >> 2);
                if (r0 < M) {
                    g_as[r0 * NHEADS + hh] = pas[im * 2];
                    g_ad[r0 * NHEADS + hh] = pad_[im * 2];
                }
                if (r0 + 8 < M) {
                    g_as[(r0 + 8) * NHEADS + hh] = pas[im * 2 + 1];
                    g_ad[(r0 + 8) * NHEADS + hh] = pad_[im * 2 + 1];
                }
            }
        }
    }
}

// ---------------- segment softmax pass 1 only: e + constant C ----------------
__global__ void stats_kernel() {
    int lane = threadIdx.x & 31;
    int warp = (blockIdx.x * blockDim.x + threadIdx.x) >> 5;
    int sub = lane >> 3, hh = lane & 7;
    int n = warp * 4 + sub;
    if (n >= N_NODES) return;
    int row = g_rowptr[n], end = g_rowptr[n + 1];
    float ad = g_ad[n * NHEADS + hh];
    float m = -INFINITY, s = 0.f;
    for (int j = row; j < end; j++) {
        int src = g_src_sorted[j];
        float e = g_as[src * NHEADS + hh] + ad;
        e = (e > 0.f) ? e : NEG_SLOPE * e;
        g_alpha[(size_t)j * NHEADS + hh] = e;
        float nm = fmaxf(m, e);
        s = s * __expf(m - nm) + __expf(e - nm);
        m = nm;
    }
    g_C[n * NHEADS + hh] = m + __logf(s + 1e-16f);
}

// ---------------- heavy aggregation (alpha = exp(e - C) inline) ----------------
__device__ __forceinline__ uint32_t pack_bf2(float a, float b) {
    __nv_bfloat162 t;
    t.x = __float2bfloat16_rn(a);
    t.y = __float2bfloat16_rn(b);
    return *(uint32_t*)&t;
}

__global__ void __launch_bounds__(128) aggregate_kernel(const float* __restrict__ hin,
                                                        const float* __restrict__ bias,
                                                        __nv_bfloat16* __restrict__ xhi,
                                                        __nv_bfloat16* __restrict__ xlo,
                                                        float* __restrict__ outp,
                                                        int mode) {
    __shared__ float4 sm4[HCDIM / 4];
    int n = blockIdx.x;
    int tid = threadIdx.x;
    int head = tid >> 4;
    int row = g_rowptr[n], end = g_rowptr[n + 1];
    float Cc = __ldg(&g_C[n * NHEADS + head]);
    const float4* h4 = (const float4*)hin;
    float4 acc = make_float4(0.f, 0.f, 0.f, 0.f);
    int j = row;
    for (; j + 1 < end; j += 2) {
        int s0 = __ldg(&g_src_sorted[j]);
        int s1 = __ldg(&g_src_sorted[j + 1]);
        float a0 = __expf(__ldg(&g_alpha[(size_t)j * NHEADS + head]) - Cc);
        float a1 = __expf(__ldg(&g_alpha[(size_t)(j + 1) * NHEADS + head]) - Cc);
        float4 v0 = __ldg(&h4[(long long)s0 * (HCDIM / 4) + tid]);
        float4 v1 = __ldg(&h4[(long long)s1 * (HCDIM / 4) + tid]);
        acc.x = fmaf(a0, v0.x, fmaf(a1, v1.x, acc.x));
        acc.y = fmaf(a0, v0.y, fmaf(a1, v1.y, acc.y));
        acc.z = fmaf(a0, v0.z, fmaf(a1, v1.z, acc.z));
        acc.w = fmaf(a0, v0.w, fmaf(a1, v1.w, acc.w));
    }
    if (j < end) {
        int s0 = __ldg(&g_src_sorted[j]);
        float a0 = __expf(__ldg(&g_alpha[(size_t)j * NHEADS + head]) - Cc);
        float4 v0 = __ldg(&h4[(long long)s0 * (HCDIM / 4) + tid]);
        acc.x = fmaf(a0, v0.x, acc.x);
        acc.y = fmaf(a0, v0.y, acc.y);
        acc.z = fmaf(a0, v0.z, acc.z);
        acc.w = fmaf(a0, v0.w, acc.w);
    }
    if (mode == 0) {
        float4 b4 = ((const float4*)bias)[tid];
        float vx = acc.x + b4.x; vx = (vx > 0.f) ? vx : expm1f(vx);
        float vy = acc.y + b4.y; vy = (vy > 0.f) ? vy : expm1f(vy);
        float vz = acc.z + b4.z; vz = (vz > 0.f) ? vz : expm1f(vz);
        float vw = acc.w + b4.w; vw = (vw > 0.f) ? vw : expm1f(vw);
        __nv_bfloat16 hx = __float2bfloat16_rn(vx), hy = __float2bfloat16_rn(vy);
        __nv_bfloat16 hz = __float2bfloat16_rn(vz), hw = __float2bfloat16_rn(vw);
        float lx = vx - __bfloat162float(hx), ly = vy - __bfloat162float(hy);
        float lz = vz - __bfloat162float(hz), lw = vw - __bfloat162float(hw);
        size_t base = ((size_t)n * HCDIM + tid * 4) >> 1;
        uint32_t* hip = (uint32_t*)xhi;
        uint32_t* lop = (uint32_t*)xlo;
        __nv_bfloat162 h01; h01.x = hx; h01.y = hy;
        __nv_bfloat162 h23; h23.x = hz; h23.y = hw;
        hip[base]     = *(uint32_t*)&h01;
        hip[base + 1] = *(uint32_t*)&h23;
        lop[base]     = pack_bf2(lx, ly);
        lop[base + 1] = pack_bf2(lz, lw);
    } else {
        sm4[tid] = acc;
        __syncthreads();
        if (tid < 16) {
            float4 s = make_float4(0.f, 0.f, 0.f, 0.f);
#pragma unroll
            for (int hh = 0; hh < NHEADS; hh++) {
                float4 f = sm4[hh * 16 + tid];
                s.x += f.x; s.y += f.y; s.z += f.z; s.w += f.w;
            }
            float4 b4 = ((const float4*)bias)[tid];
            float4 o;
            o.x = s.x * (1.0f / NHEADS) + b4.x;
            o.y = s.y * (1.0f / NHEADS) + b4.y;
            o.z = s.z * (1.0f / NHEADS) + b4.z;
            o.w = s.w * (1.0f / NHEADS) + b4.w;
            ((float4*)outp)[(long long)n * (CDIM / 4) + tid] = o;
        }
    }
}

// ---------------- final projection ----------------
__global__ void __launch_bounds__(256) proj_kernel(const float* __restrict__ x3,
                                                   const float* __restrict__ Wout,
                                                   const float* __restrict__ bout,
                                                   float* __restrict__ out) {
    __shared__ float Ws[CDIM * 16];
    __shared__ float bs[16];
    int tid = threadIdx.x;
    for (int idx = tid; idx < CDIM * 16; idx += 256) {
        int c = idx >> 4, o = idx & 15;
        Ws[idx] = (o < OUT_DIM) ? Wout[c * OUT_DIM + o] : 0.f;
    }
    if (tid < 16) bs[tid] = (tid < OUT_DIM) ? bout[tid] : 0.f;
    __syncthreads();
    int tx = tid & 15;
    int tn = tid >> 4;
    int n = blockIdx.x * 16 + tn;
    if (n >= N_NODES) return;
    const float* xr = x3 + (long long)n * CDIM;
    float acc = 0.f;
#pragma unroll
    for (int c = 0; c < CDIM; c++) acc += xr[c] * Ws[c * 16 + tx];
    if (tx < OUT_DIM) out[(long long)n * OUT_DIM + tx] = acc + bs[tx];
}

// ---------------- launch ----------------
extern "C" void kernel_launch(void* const* d_in, const int* in_sizes, int n_in,
                              void* d_out, int out_size) {
    const float* x    = (const float*)d_in[0];
    const int*   ei   = (const int*)d_in[1];
    const float* W1   = (const float*)d_in[2];
    const float* a1s  = (const float*)d_in[3];
    const float* a1d  = (const float*)d_in[4];
    const float* b1   = (const float*)d_in[5];
    const float* W2   = (const float*)d_in[6];
    const float* a2s  = (const float*)d_in[7];
    const float* a2d  = (const float*)d_in[8];
    const float* b2   = (const float*)d_in[9];
    const float* W3   = (const float*)d_in[10];
    const float* a3s  = (const float*)d_in[11];
    const float* a3d  = (const float*)d_in[12];
    const float* b3   = (const float*)d_in[13];
    const float* Wout = (const float*)d_in[14];
    const float* bout = (const float*)d_in[15];
    float* out = (float*)d_out;

    float *p_h, *p_x3;
    __nv_bfloat16 *p_xhi, *p_xlo, *p_w2hi, *p_w2lo, *p_w3hi, *p_w3lo;
    cudaGetSymbolAddress((void**)&p_h,    g_h);
    cudaGetSymbolAddress((void**)&p_x3,   g_x3);
    cudaGetSymbolAddress((void**)&p_xhi,  g_xhi);
    cudaGetSymbolAddress((void**)&p_xlo,  g_xlo);
    cudaGetSymbolAddress((void**)&p_w2hi, g_w2hi);
    cudaGetSymbolAddress((void**)&p_w2lo, g_w2lo);
    cudaGetSymbolAddress((void**)&p_w3hi, g_w3hi);
    cudaGetSymbolAddress((void**)&p_w3lo, g_w3lo);

    cudaFuncSetAttribute(mma_gemm_kernel, cudaFuncAttributeMaxDynamicSharedMemorySize, GSMEM);

    const int scan_blocks = (N_NODES + 1023) / 1024;

    detect_kernel<<<1, 256>>>(ei);
    init_counts_kernel<<<(N_NODES + 255) / 256, 256>>>();
    count_kernel<<<(NE + 255) / 256, 256>>>(ei);
    scan_block_kernel<<<scan_blocks, 1024>>>();
    scan_mid_kernel<<<1, 32>>>(scan_blocks);
    scan_add_kernel<<<scan_blocks, 1024>>>();
    fill_kernel<<<(E_TOT + 255) / 256, 256>>>(ei);

    int wsplit_blocks = (HCDIM * HCDIM + 255) / 256;
    wsplit_kernel<<<wsplit_blocks, 256>>>(W2, p_w2hi, p_w2lo);
    wsplit_kernel<<<wsplit_blocks, 256>>>(W3, p_w3hi, p_w3lo);

    dim3 sgrid(HCDIM / BN, (N_NODES + BM - 1) / BM);
    dim3 mgrid(HCDIM / 128, (N_NODES + 127) / 128);
    int stats_blocks = (N_NODES + 31) / 32;

    // ---- layer 1 (alpha fused into gemm_small epilogue) ----
    gemm_small_kernel<<<sgrid, 256>>>(x, W1, a1s, a1d, p_h, N_NODES, F_IN, HCDIM);
    stats_kernel<<<stats_blocks, 256>>>();
    aggregate_kernel<<<N_NODES, 128>>>(p_h, b1, p_xhi, p_xlo, nullptr, 0);

    // ---- layer 2 ----
    mma_gemm_kernel<<<mgrid, 256, GSMEM>>>(p_xhi, p_xlo, p_w2hi, p_w2lo, a2s, a2d, p_h, N_NODES);
    stats_kernel<<<stats_blocks, 256>>>();
    aggregate_kernel<<<N_NODES, 128>>>(p_h, b2, p_xhi, p_xlo, nullptr, 0);

    // ---- layer 3 ----
    mma_gemm_kernel<<<mgrid, 256, GSMEM>>>(p_xhi, p_xlo, p_w3hi, p_w3lo, a3s, a3d, p_h, N_NODES);
    stats_kernel<<<stats_blocks, 256>>>();
    aggregate_kernel<<<N_NODES, 128>>>(p_h, b3, nullptr, nullptr, p_x3, 1);

    // ---- output projection ----
    proj_kernel<<<(N_NODES + 15) / 16, 256>>>(p_x3, Wout, bout, out);
}

// round 10
// speedup vs baseline: 3.3873x; 1.0491x over previous
#include <cuda_runtime.h>
#include <cuda_bf16.h>
#include <cuda_fp16.h>
#include <cstdint>
#include <stdint.h>
#include <math.h>

#define N_NODES 50000
#define F_IN    18
#define NHEADS  8
#define CDIM    64
#define HCDIM   512
#define NE      400000
#define E_TOT   (NE + N_NODES)
#define OUT_DIM 15
#define NEG_SLOPE 0.2f

// ---------------- scratch (static device globals; no runtime allocation) ----------------
__device__ __half g_h [N_NODES * HCDIM];          // post-GEMM features (fp16: halves gather BW)
__device__ float g_x3[N_NODES * CDIM];
__device__ __nv_bfloat16 g_xhi[N_NODES * HCDIM];
__device__ __nv_bfloat16 g_xlo[N_NODES * HCDIM];
__device__ __nv_bfloat16 g_w2hi[HCDIM * HCDIM];
__device__ __nv_bfloat16 g_w2lo[HCDIM * HCDIM];
__device__ __nv_bfloat16 g_w3hi[HCDIM * HCDIM];
__device__ __nv_bfloat16 g_w3lo[HCDIM * HCDIM];
__device__ float g_as[N_NODES * NHEADS];
__device__ float g_ad[N_NODES * NHEADS];
__device__ float g_C [N_NODES * NHEADS];          // softmax constant: m + log(s+eps)
__device__ float g_alpha[(size_t)E_TOT * NHEADS]; // stores raw e (LeakyReLU'd logits)
__device__ int   g_src_sorted[E_TOT];
__device__ int   g_rowptr[N_NODES + 1];
__device__ int   g_cursor[N_NODES];
__device__ int   g_counts[N_NODES];
__device__ int   g_part[64];
__device__ int   g_is64;

// ---------------- PTX helpers (portable: sm_80-era features only) ----------------
__device__ __forceinline__ uint32_t smem_u32(const void* p) {
    uint32_t a;
    asm("{ .reg .u64 t; cvta.to.shared.u64 t, %1; cvt.u32.u64 %0, t; }" : "=r"(a) : "l"(p));
    return a;
}
static __device__ __forceinline__ void cp_async16(uint32_t dst, const void* src, int sz) {
    asm volatile("cp.async.cg.shared.global [%0], [%1], 16, %2;\n"
                 :: "r"(dst), "l"(src), "r"(sz) : "memory");
}
static __device__ __forceinline__ void cp_commit() {
    asm volatile("cp.async.commit_group;" ::: "memory");
}
static __device__ __forceinline__ void cp_wait0() {
    asm volatile("cp.async.wait_group 0;" ::: "memory");
}
static __device__ __forceinline__ void cp_wait1() {
    asm volatile("cp.async.wait_group 1;" ::: "memory");
}

#define LDSM_X4(r, addr) \
    asm volatile("ldmatrix.sync.aligned.m8n8.x4.shared.b16 {%0,%1,%2,%3}, [%4];" \
        : "=r"((r)[0]), "=r"((r)[1]), "=r"((r)[2]), "=r"((r)[3]) : "r"(addr))
// B operand: [K,N] k-row-major tile -> column fragments for TWO 8-col blocks at once
#define LDSM_X4_TRANS(r, addr) \
    asm volatile("ldmatrix.sync.aligned.m8n8.x4.trans.shared.b16 {%0,%1,%2,%3}, [%4];" \
        : "=r"((r)[0]), "=r"((r)[1]), "=r"((r)[2]), "=r"((r)[3]) : "r"(addr))
#define MMA_BF16(c, a, b) \
    asm volatile("mma.sync.aligned.m16n8k16.row.col.f32.bf16.bf16.f32 " \
        "{%0,%1,%2,%3},{%4,%5,%6,%7},{%8,%9},{%0,%1,%2,%3};" \
        : "+f"((c)[0]), "+f"((c)[1]), "+f"((c)[2]), "+f"((c)[3]) \
        : "r"((a)[0]), "r"((a)[1]), "r"((a)[2]), "r"((a)[3]), "r"((b)[0]), "r"((b)[1]))

// ---------------- edge dtype handling ----------------
__device__ __forceinline__ int edge_at(const int* p, int idx) {
    return g_is64 ? p[2 * idx] : p[idx];
}

__global__ void detect_kernel(const int* __restrict__ p) {
    __shared__ int red[256];
    int acc = 0;
    for (int i = threadIdx.x; i < 8192; i += 256) acc |= p[2 * i + 1];
    red[threadIdx.x] = acc;
    __syncthreads();
    for (int s = 128; s > 0; s >>= 1) {
        if (threadIdx.x < s) red[threadIdx.x] |= red[threadIdx.x + s];
        __syncthreads();
    }
    if (threadIdx.x == 0) g_is64 = (red[0] == 0) ? 1 : 0;
}

// ---------------- CSR build ----------------
__global__ void init_counts_kernel() {
    int i = blockIdx.x * blockDim.x + threadIdx.x;
    if (i < N_NODES) g_counts[i] = 1;
}
__global__ void count_kernel(const int* __restrict__ ei) {
    int i = blockIdx.x * blockDim.x + threadIdx.x;
    if (i < NE) atomicAdd(&g_counts[edge_at(ei, NE + i)], 1);
}
__global__ void __launch_bounds__(1024) scan_block_kernel() {
    __shared__ int sm[1024];
    int i = blockIdx.x * 1024 + threadIdx.x;
    int v = (i < N_NODES) ? g_counts[i] : 0;
    sm[threadIdx.x] = v;
    __syncthreads();
    for (int off = 1; off < 1024; off <<= 1) {
        int t = (threadIdx.x >= off) ? sm[threadIdx.x - off] : 0;
        __syncthreads();
        sm[threadIdx.x] += t;
        __syncthreads();
    }
    if (i < N_NODES) g_rowptr[i] = sm[threadIdx.x] - v;
    if (threadIdx.x == 1023) g_part[blockIdx.x] = sm[1023];
}
__global__ void scan_mid_kernel(int nblocks) {
    if (threadIdx.x == 0) {
        int run = 0;
        for (int b = 0; b < nblocks; b++) { int t = g_part[b]; g_part[b] = run; run += t; }
    }
}
__global__ void __launch_bounds__(1024) scan_add_kernel() {
    int i = blockIdx.x * 1024 + threadIdx.x;
    if (i < N_NODES) {
        int v = g_rowptr[i] + g_part[blockIdx.x];
        g_rowptr[i] = v;
        g_cursor[i] = v;
    }
    if (i == 0) g_rowptr[N_NODES] = E_TOT;
}
__global__ void fill_kernel(const int* __restrict__ ei) {
    int i = blockIdx.x * blockDim.x + threadIdx.x;
    if (i >= E_TOT) return;
    int src, dst;
    if (i < NE) { src = edge_at(ei, i); dst = edge_at(ei, NE + i); }
    else        { src = dst = i - NE; }
    int pos = atomicAdd(&g_cursor[dst], 1);
    g_src_sorted[pos] = src;
}

// ---------------- small-K GEMM (layer 1, K=18) with fused alpha epilogue ----------------
// BN=64 => a block's column tile is exactly one head (blockIdx.x).
#define BM 128
#define BN 64
#define BK 16

__global__ void __launch_bounds__(256) gemm_small_kernel(const float* __restrict__ A,
                                                         const float* __restrict__ B,
                                                         const float* __restrict__ a_src,
                                                         const float* __restrict__ a_dst,
                                                         __half* __restrict__ C,
                                                         int M, int K, int Nc) {
    __shared__ float As[BK][BM + 4];
    __shared__ float Bs[BK][BN + 4];
    int tid = threadIdx.x;
    int bn0 = blockIdx.x * BN;
    int bm0 = blockIdx.y * BM;
    int tr = tid >> 4;
    int tc = tid & 15;
    int a_row = tid >> 1;
    int a_cb  = (tid & 1) * 8;
    int b_row = tid >> 4;
    int b_col = (tid & 15) * 4;

    float acc[8][4];
#pragma unroll
    for (int i = 0; i < 8; i++)
#pragma unroll
        for (int j = 0; j < 4; j++) acc[i][j] = 0.f;

    for (int k0 = 0; k0 < K; k0 += BK) {
        int gm = bm0 + a_row;
#pragma unroll
        for (int i = 0; i < 8; i++) {
            int gk = k0 + a_cb + i;
            As[a_cb + i][a_row] = (gm < M && gk < K) ? A[(long long)gm * K + gk] : 0.f;
        }
        {
            int gk = k0 + b_row;
            float4 bv = make_float4(0.f, 0.f, 0.f, 0.f);
            if (gk < K) bv = *(const float4*)&B[(long long)gk * Nc + bn0 + b_col];
            *(float4*)&Bs[b_row][b_col] = bv;
        }
        __syncthreads();
#pragma unroll
        for (int kk = 0; kk < BK; kk++) {
            float a[8], b[4];
#pragma unroll
            for (int i = 0; i < 8; i++) a[i] = As[kk][tr * 8 + i];
#pragma unroll
            for (int j = 0; j < 4; j++) b[j] = Bs[kk][tc * 4 + j];
#pragma unroll
            for (int i = 0; i < 8; i++)
#pragma unroll
                for (int j = 0; j < 4; j++) acc[i][j] += a[i] * b[j];
        }
        __syncthreads();
    }
#pragma unroll
    for (int i = 0; i < 8; i++) {
        int gm = bm0 + tr * 8 + i;
        if (gm < M) {
            __half2 h01 = __floats2half2_rn(acc[i][0], acc[i][1]);
            __half2 h23 = __floats2half2_rn(acc[i][2], acc[i][3]);
            uint2 u;
            u.x = *(uint32_t*)&h01;
            u.y = *(uint32_t*)&h23;
            *(uint2*)&C[(size_t)gm * Nc + bn0 + tc * 4] = u;
        }
    }

    // fused alpha for this head: dots over the 64 columns, reduce over the 16 tc lanes
    {
        int hh = blockIdx.x;
        float pas[8], pad_[8];
#pragma unroll
        for (int i = 0; i < 8; i++) { pas[i] = 0.f; pad_[i] = 0.f; }
#pragma unroll
        for (int j = 0; j < 4; j++) {
            float sj = __ldg(&a_src[hh * CDIM + tc * 4 + j]);
            float dj = __ldg(&a_dst[hh * CDIM + tc * 4 + j]);
#pragma unroll
            for (int i = 0; i < 8; i++) {
                pas[i]  = fmaf(acc[i][j], sj, pas[i]);
                pad_[i] = fmaf(acc[i][j], dj, pad_[i]);
            }
        }
#pragma unroll
        for (int off = 1; off < 16; off <<= 1) {
#pragma unroll
            for (int i = 0; i < 8; i++) {
                pas[i]  += __shfl_xor_sync(0xffffffffu, pas[i], off);
                pad_[i] += __shfl_xor_sync(0xffffffffu, pad_[i], off);
            }
        }
        if (tc == 0) {
#pragma unroll
            for (int i = 0; i < 8; i++) {
                int gm = bm0 + tr * 8 + i;
                if (gm < M) {
                    g_as[gm * NHEADS + hh] = pas[i];
                    g_ad[gm * NHEADS + hh] = pad_[i];
                }
            }
        }
    }
}

// ---------------- W bf16 split (elementwise, native [K][N] layout kept) ----------------
__global__ void __launch_bounds__(256) wsplit_kernel(const float* __restrict__ W,
                                                     __nv_bfloat16* __restrict__ whi,
                                                     __nv_bfloat16* __restrict__ wlo) {
    int i = blockIdx.x * blockDim.x + threadIdx.x;
    if (i < HCDIM * HCDIM) {
        float v = W[i];
        __nv_bfloat16 hi = __float2bfloat16_rn(v);
        whi[i] = hi;
        wlo[i] = __float2bfloat16_rn(v - __bfloat162float(hi));
    }
}

// ---------------- mma.sync bf16-split GEMM + fused alpha epilogue ----------------
#define KTILES  (HCDIM / 32)      // 16
#define APITCH  80
#define BPITCH  272
#define A_TB    (128 * APITCH)
#define B_TB    (32 * BPITCH)
#define BUF_B   (2 * A_TB + 2 * B_TB)
#define GSMEM   (2 * BUF_B)

__global__ void __launch_bounds__(256, 2)
mma_gemm_kernel(const __nv_bfloat16* __restrict__ Ahi,
                const __nv_bfloat16* __restrict__ Alo,
                const __nv_bfloat16* __restrict__ Whi,
                const __nv_bfloat16* __restrict__ Wlo,
                const float* __restrict__ a_src,
                const float* __restrict__ a_dst,
                __half* __restrict__ C, int M) {
    extern __shared__ char smem[];
    uint32_t sb = smem_u32(smem);
    int tid = threadIdx.x, lane = tid & 31, wid = tid >> 5;
    int wm = wid & 3, wn = wid >> 2;
    int bm0 = blockIdx.y * 128, bn0 = blockIdx.x * 128;

    float acc[2][8][4];
#pragma unroll
    for (int im = 0; im < 2; im++)
#pragma unroll
        for (int in_ = 0; in_ < 8; in_++)
#pragma unroll
            for (int q = 0; q < 4; q++) acc[im][in_][q] = 0.f;

    auto load_tile = [&](int kt, int b) {
        uint32_t base = sb + (uint32_t)b * BUF_B;
#pragma unroll
        for (int m = 0; m < 2; m++) {
            const __nv_bfloat16* srcm = m ? Alo : Ahi;
            uint32_t tb = base + (uint32_t)m * A_TB;
#pragma unroll
            for (int q = 0; q < 2; q++) {
                int idx = q * 256 + tid;
                int r = idx >> 2, ch = idx & 3;
                int gr = bm0 + r;
                int sz = 16;
                if (gr >= M) { gr = 0; sz = 0; }
                cp_async16(tb + (uint32_t)(r * APITCH + ch * 16),
                           srcm + (size_t)gr * HCDIM + kt * 32 + ch * 8, sz);
            }
        }
#pragma unroll
        for (int m = 0; m < 2; m++) {
            const __nv_bfloat16* srcm = m ? Wlo : Whi;
            uint32_t tb = base + 2 * A_TB + (uint32_t)m * B_TB;
#pragma unroll
            for (int q = 0; q < 2; q++) {
                int idx = q * 256 + tid;
                int r = idx >> 4, ch = idx & 15;
                cp_async16(tb + (uint32_t)(r * BPITCH + ch * 16),
                           srcm + (size_t)(kt * 32 + r) * HCDIM + bn0 + ch * 8, 16);
            }
        }
        cp_commit();
    };

    load_tile(0, 0);

    for (int t = 0; t < KTILES; t++) {
        int b = t & 1;
        if (t + 1 < KTILES) { load_tile(t + 1, b ^ 1); cp_wait1(); }
        else cp_wait0();
        __syncthreads();

        uint32_t abase = sb + (uint32_t)b * BUF_B;
        uint32_t bbase = abase + 2 * A_TB;
#pragma unroll
        for (int ks = 0; ks < 2; ks++) {
            uint32_t ah[2][4], al[2][4];
#pragma unroll
            for (int im = 0; im < 2; im++) {
                uint32_t ra = abase
                    + (uint32_t)((wm * 32 + im * 16 + (lane & 15)) * APITCH
                                 + (ks * 16 + (lane >> 4) * 8) * 2);
                LDSM_X4(ah[im], ra);
                LDSM_X4(al[im], ra + A_TB);
            }
            // B: x4.trans covers two 8-col blocks per instruction
            int g = lane >> 3;
#pragma unroll
            for (int in2 = 0; in2 < 4; in2++) {
                uint32_t rb = bbase
                    + (uint32_t)((ks * 16 + (lane & 7) + (g & 1) * 8) * BPITCH
                                 + (wn * 64 + in2 * 16 + (g >> 1) * 8) * 2);
                uint32_t bh[4], bl[4];
                LDSM_X4_TRANS(bh, rb);
                LDSM_X4_TRANS(bl, rb + B_TB);
#pragma unroll
                for (int im = 0; im < 2; im++) {
                    MMA_BF16(acc[im][in2 * 2],     ah[im], (bh + 0));
                    MMA_BF16(acc[im][in2 * 2],     ah[im], (bl + 0));
                    MMA_BF16(acc[im][in2 * 2],     al[im], (bh + 0));
                    MMA_BF16(acc[im][in2 * 2 + 1], ah[im], (bh + 2));
                    MMA_BF16(acc[im][in2 * 2 + 1], ah[im], (bl + 2));
                    MMA_BF16(acc[im][in2 * 2 + 1], al[im], (bh + 2));
                }
            }
        }
        __syncthreads();
    }

    // ---- C store (fp16) ----
#pragma unroll
    for (int im = 0; im < 2; im++) {
        int r0 = bm0 + wm * 32 + im * 16 + (lane >> 2);
#pragma unroll
        for (int in_ = 0; in_ < 8; in_++) {
            int col = bn0 + wn * 64 + in_ * 8 + (lane & 3) * 2;
            if (r0 < M) {
                __half2 hp = __floats2half2_rn(acc[im][in_][0], acc[im][in_][1]);
                *(uint32_t*)&C[(size_t)r0 * HCDIM + col] = *(uint32_t*)&hp;
            }
            if (r0 + 8 < M) {
                __half2 hp = __floats2half2_rn(acc[im][in_][2], acc[im][in_][3]);
                *(uint32_t*)&C[(size_t)(r0 + 8) * HCDIM + col] = *(uint32_t*)&hp;
            }
        }
    }

    // ---- fused alpha: warp's 64 cols = one head ----
    {
        int hh = (bn0 >> 6) + wn;
        float pas[4] = {0.f, 0.f, 0.f, 0.f};
        float pad_[4] = {0.f, 0.f, 0.f, 0.f};
#pragma unroll
        for (int in_ = 0; in_ < 8; in_++) {
            int c0 = in_ * 8 + (lane & 3) * 2;
            float s0 = __ldg(&a_src[hh * CDIM + c0]);
            float s1 = __ldg(&a_src[hh * CDIM + c0 + 1]);
            float d0 = __ldg(&a_dst[hh * CDIM + c0]);
            float d1 = __ldg(&a_dst[hh * CDIM + c0 + 1]);
#pragma unroll
            for (int im = 0; im < 2; im++) {
                pas[im * 2]     += acc[im][in_][0] * s0 + acc[im][in_][1] * s1;
                pas[im * 2 + 1] += acc[im][in_][2] * s0 + acc[im][in_][3] * s1;
                pad_[im * 2]     += acc[im][in_][0] * d0 + acc[im][in_][1] * d1;
                pad_[im * 2 + 1] += acc[im][in_][2] * d0 + acc[im][in_][3] * d1;
            }
        }
#pragma unroll
        for (int k = 0; k < 4; k++) {
            pas[k]  += __shfl_xor_sync(0xffffffffu, pas[k], 1);
            pas[k]  += __shfl_xor_sync(0xffffffffu, pas[k], 2);
            pad_[k] += __shfl_xor_sync(0xffffffffu, pad_[k], 1);
            pad_[k] += __shfl_xor_sync(0xffffffffu, pad_[k], 2);
        }
        if ((lane & 3) == 0) {
#pragma unroll
            for (int im = 0; im < 2; im++) {
                int r0 = bm0 + wm * 32 + im * 16 + (lane >> 2);
                if (r0 < M) {
                    g_as[r0 * NHEADS + hh] = pas[im * 2];
                    g_ad[r0 * NHEADS + hh] = pad_[im * 2];
                }
                if (r0 + 8 < M) {
                    g_as[(r0 + 8) * NHEADS + hh] = pas[im * 2 + 1];
                    g_ad[(r0 + 8) * NHEADS + hh] = pad_[im * 2 + 1];
                }
            }
        }
    }
}

// ---------------- segment softmax: warp per node, 4 edges x 8 heads per iter ----------------
__global__ void stats_kernel() {
    int lane = threadIdx.x & 31;
    int n = (blockIdx.x * blockDim.x + threadIdx.x) >> 5;
    int hh = lane & 7, sub = lane >> 3;
    if (n >= N_NODES) return;
    int row = g_rowptr[n], end = g_rowptr[n + 1];
    float ad = g_ad[n * NHEADS + hh];
    float m = -1e30f, s = 0.f;
    for (int j = row + sub; j < end; j += 4) {
        int src = g_src_sorted[j];
        float e = g_as[src * NHEADS + hh] + ad;
        e = (e > 0.f) ? e : NEG_SLOPE * e;
        g_alpha[(size_t)j * NHEADS + hh] = e;
        float nm = fmaxf(m, e);
        s = s * __expf(m - nm) + __expf(e - nm);
        m = nm;
    }
    // merge the 4 sub-lane partials (lanes differ in bits 3,4)
#pragma unroll
    for (int off = 8; off <= 16; off <<= 1) {
        float mo = __shfl_xor_sync(0xffffffffu, m, off);
        float so = __shfl_xor_sync(0xffffffffu, s, off);
        float nm = fmaxf(m, mo);
        s = s * __expf(m - nm) + so * __expf(mo - nm);
        m = nm;
    }
    if (sub == 0) g_C[n * NHEADS + hh] = m + __logf(s + 1e-16f);
}

// ---------------- heavy aggregation (fp16 h, alpha = exp(e - C) inline) ----------------
__device__ __forceinline__ uint32_t pack_bf2(float a, float b) {
    __nv_bfloat162 t;
    t.x = __float2bfloat16_rn(a);
    t.y = __float2bfloat16_rn(b);
    return *(uint32_t*)&t;
}

__global__ void __launch_bounds__(128) aggregate_kernel(const __half* __restrict__ hin,
                                                        const float* __restrict__ bias,
                                                        __nv_bfloat16* __restrict__ xhi,
                                                        __nv_bfloat16* __restrict__ xlo,
                                                        float* __restrict__ outp,
                                                        int mode) {
    __shared__ float4 sm4[HCDIM / 4];
    int n = blockIdx.x;
    int tid = threadIdx.x;
    int head = tid >> 4;
    int row = g_rowptr[n], end = g_rowptr[n + 1];
    float Cc = __ldg(&g_C[n * NHEADS + head]);
    const uint2* h2 = (const uint2*)hin;   // 8 B = 4 halves = this thread's 4 channels
    float4 acc = make_float4(0.f, 0.f, 0.f, 0.f);
    int j = row;
    for (; j + 1 < end; j += 2) {
        int s0 = __ldg(&g_src_sorted[j]);
        int s1 = __ldg(&g_src_sorted[j + 1]);
        float a0 = __expf(__ldg(&g_alpha[(size_t)j * NHEADS + head]) - Cc);
        float a1 = __expf(__ldg(&g_alpha[(size_t)(j + 1) * NHEADS + head]) - Cc);
        uint2 u0 = __ldg(&h2[(size_t)s0 * (HCDIM / 4) + tid]);
        uint2 u1 = __ldg(&h2[(size_t)s1 * (HCDIM / 4) + tid]);
        float2 f0a = __half22float2(*(__half2*)&u0.x);
        float2 f0b = __half22float2(*(__half2*)&u0.y);
        float2 f1a = __half22float2(*(__half2*)&u1.x);
        float2 f1b = __half22float2(*(__half2*)&u1.y);
        acc.x = fmaf(a0, f0a.x, fmaf(a1, f1a.x, acc.x));
        acc.y = fmaf(a0, f0a.y, fmaf(a1, f1a.y, acc.y));
        acc.z = fmaf(a0, f0b.x, fmaf(a1, f1b.x, acc.z));
        acc.w = fmaf(a0, f0b.y, fmaf(a1, f1b.y, acc.w));
    }
    if (j < end) {
        int s0 = __ldg(&g_src_sorted[j]);
        float a0 = __expf(__ldg(&g_alpha[(size_t)j * NHEADS + head]) - Cc);
        uint2 u0 = __ldg(&h2[(size_t)s0 * (HCDIM / 4) + tid]);
        float2 f0a = __half22float2(*(__half2*)&u0.x);
        float2 f0b = __half22float2(*(__half2*)&u0.y);
        acc.x = fmaf(a0, f0a.x, acc.x);
        acc.y = fmaf(a0, f0a.y, acc.y);
        acc.z = fmaf(a0, f0b.x, acc.z);
        acc.w = fmaf(a0, f0b.y, acc.w);
    }
    if (mode == 0) {
        float4 b4 = ((const float4*)bias)[tid];
        float vx = acc.x + b4.x; vx = (vx > 0.f) ? vx : expm1f(vx);
        float vy = acc.y + b4.y; vy = (vy > 0.f) ? vy : expm1f(vy);
        float vz = acc.z + b4.z; vz = (vz > 0.f) ? vz : expm1f(vz);
        float vw = acc.w + b4.w; vw = (vw > 0.f) ? vw : expm1f(vw);
        __nv_bfloat16 hx = __float2bfloat16_rn(vx), hy = __float2bfloat16_rn(vy);
        __nv_bfloat16 hz = __float2bfloat16_rn(vz), hw = __float2bfloat16_rn(vw);
        float lx = vx - __bfloat162float(hx), ly = vy - __bfloat162float(hy);
        float lz = vz - __bfloat162float(hz), lw = vw - __bfloat162float(hw);
        size_t base = ((size_t)n * HCDIM + tid * 4) >> 1;
        uint32_t* hip = (uint32_t*)xhi;
        uint32_t* lop = (uint32_t*)xlo;
        __nv_bfloat162 h01; h01.x = hx; h01.y = hy;
        __nv_bfloat162 h23; h23.x = hz; h23.y = hw;
        hip[base]     = *(uint32_t*)&h01;
        hip[base + 1] = *(uint32_t*)&h23;
        lop[base]     = pack_bf2(lx, ly);
        lop[base + 1] = pack_bf2(lz, lw);
    } else {
        sm4[tid] = acc;
        __syncthreads();
        if (tid < 16) {
            float4 s = make_float4(0.f, 0.f, 0.f, 0.f);
#pragma unroll
            for (int hh = 0; hh < NHEADS; hh++) {
                float4 f = sm4[hh * 16 + tid];
                s.x += f.x; s.y += f.y; s.z += f.z; s.w += f.w;
            }
            float4 b4 = ((const float4*)bias)[tid];
            float4 o;
            o.x = s.x * (1.0f / NHEADS) + b4.x;
            o.y = s.y * (1.0f / NHEADS) + b4.y;
            o.z = s.z * (1.0f / NHEADS) + b4.z;
            o.w = s.w * (1.0f / NHEADS) + b4.w;
            ((float4*)outp)[(long long)n * (CDIM / 4) + tid] = o;
        }
    }
}

// ---------------- final projection ----------------
__global__ void __launch_bounds__(256) proj_kernel(const float* __restrict__ x3,
                                                   const float* __restrict__ Wout,
                                                   const float* __restrict__ bout,
                                                   float* __restrict__ out) {
    __shared__ float Ws[CDIM * 16];
    __shared__ float bs[16];
    int tid = threadIdx.x;
    for (int idx = tid; idx < CDIM * 16; idx += 256) {
        int c = idx >> 4, o = idx & 15;
        Ws[idx] = (o < OUT_DIM) ? Wout[c * OUT_DIM + o] : 0.f;
    }
    if (tid < 16) bs[tid] = (tid < OUT_DIM) ? bout[tid] : 0.f;
    __syncthreads();
    int tx = tid & 15;
    int tn = tid >> 4;
    int n = blockIdx.x * 16 + tn;
    if (n >= N_NODES) return;
    const float* xr = x3 + (long long)n * CDIM;
    float acc = 0.f;
#pragma unroll
    for (int c = 0; c < CDIM; c++) acc += xr[c] * Ws[c * 16 + tx];
    if (tx < OUT_DIM) out[(long long)n * OUT_DIM + tx] = acc + bs[tx];
}

// ---------------- launch ----------------
extern "C" void kernel_launch(void* const* d_in, const int* in_sizes, int n_in,
                              void* d_out, int out_size) {
    const float* x    = (const float*)d_in[0];
    const int*   ei   = (const int*)d_in[1];
    const float* W1   = (const float*)d_in[2];
    const float* a1s  = (const float*)d_in[3];
    const float* a1d  = (const float*)d_in[4];
    const float* b1   = (const float*)d_in[5];
    const float* W2   = (const float*)d_in[6];
    const float* a2s  = (const float*)d_in[7];
    const float* a2d  = (const float*)d_in[8];
    const float* b2   = (const float*)d_in[9];
    const float* W3   = (const float*)d_in[10];
    const float* a3s  = (const float*)d_in[11];
    const float* a3d  = (const float*)d_in[12];
    const float* b3   = (const float*)d_in[13];
    const float* Wout = (const float*)d_in[14];
    const float* bout = (const float*)d_in[15];
    float* out = (float*)d_out;

    float *p_x3;
    __half *p_h;
    __nv_bfloat16 *p_xhi, *p_xlo, *p_w2hi, *p_w2lo, *p_w3hi, *p_w3lo;
    cudaGetSymbolAddress((void**)&p_h,    g_h);
    cudaGetSymbolAddress((void**)&p_x3,   g_x3);
    cudaGetSymbolAddress((void**)&p_xhi,  g_xhi);
    cudaGetSymbolAddress((void**)&p_xlo,  g_xlo);
    cudaGetSymbolAddress((void**)&p_w2hi, g_w2hi);
    cudaGetSymbolAddress((void**)&p_w2lo, g_w2lo);
    cudaGetSymbolAddress((void**)&p_w3hi, g_w3hi);
    cudaGetSymbolAddress((void**)&p_w3lo, g_w3lo);

    cudaFuncSetAttribute(mma_gemm_kernel, cudaFuncAttributeMaxDynamicSharedMemorySize, GSMEM);

    const int scan_blocks = (N_NODES + 1023) / 1024;

    detect_kernel<<<1, 256>>>(ei);
    init_counts_kernel<<<(N_NODES + 255) / 256, 256>>>();
    count_kernel<<<(NE + 255) / 256, 256>>>(ei);
    scan_block_kernel<<<scan_blocks, 1024>>>();
    scan_mid_kernel<<<1, 32>>>(scan_blocks);
    scan_add_kernel<<<scan_blocks, 1024>>>();
    fill_kernel<<<(E_TOT + 255) / 256, 256>>>(ei);

    int wsplit_blocks = (HCDIM * HCDIM + 255) / 256;
    wsplit_kernel<<<wsplit_blocks, 256>>>(W2, p_w2hi, p_w2lo);
    wsplit_kernel<<<wsplit_blocks, 256>>>(W3, p_w3hi, p_w3lo);

    dim3 sgrid(HCDIM / BN, (N_NODES + BM - 1) / BM);
    dim3 mgrid(HCDIM / 128, (N_NODES + 127) / 128);
    int stats_blocks = (N_NODES * 32 + 255) / 256;   // warp per node

    // ---- layer 1 (alpha fused into gemm_small epilogue) ----
    gemm_small_kernel<<<sgrid, 256>>>(x, W1, a1s, a1d, p_h, N_NODES, F_IN, HCDIM);
    stats_kernel<<<stats_blocks, 256>>>();
    aggregate_kernel<<<N_NODES, 128>>>(p_h, b1, p_xhi, p_xlo, nullptr, 0);

    // ---- layer 2 ----
    mma_gemm_kernel<<<mgrid, 256, GSMEM>>>(p_xhi, p_xlo, p_w2hi, p_w2lo, a2s, a2d, p_h, N_NODES);
    stats_kernel<<<stats_blocks, 256>>>();
    aggregate_kernel<<<N_NODES, 128>>>(p_h, b2, p_xhi, p_xlo, nullptr, 0);

    // ---- layer 3 ----
    mma_gemm_kernel<<<mgrid, 256, GSMEM>>>(p_xhi, p_xlo, p_w3hi, p_w3lo, a3s, a3d, p_h, N_NODES);
    stats_kernel<<<stats_blocks, 256>>>();
    aggregate_kernel<<<N_NODES, 128>>>(p_h, b3, nullptr, nullptr, p_x3, 1);

    // ---- output projection ----
    proj_kernel<<<(N_NODES + 15) / 16, 256>>>(p_x3, Wout, bout, out);
}

// round 12
// speedup vs baseline: 3.4272x; 1.0118x over previous
#include <cuda_runtime.h>
#include <cuda_bf16.h>
#include <cuda_fp16.h>
#include <cstdint>
#include <stdint.h>
#include <math.h>

#define N_NODES 50000
#define F_IN    18
#define NHEADS  8
#define CDIM    64
#define HCDIM   512
#define NE      400000
#define E_TOT   (NE + N_NODES)
#define OUT_DIM 15
#define NEG_SLOPE 0.2f

// ---------------- scratch (static device globals; no runtime allocation) ----------------
__device__ __half g_h [N_NODES * HCDIM];          // post-GEMM features (fp16)
__device__ __nv_bfloat16 g_xhi[N_NODES * HCDIM];
__device__ __nv_bfloat16 g_xlo[N_NODES * HCDIM];
__device__ __nv_bfloat16 g_w2hi[HCDIM * HCDIM];
__device__ __nv_bfloat16 g_w2lo[HCDIM * HCDIM];
__device__ __nv_bfloat16 g_w3hi[HCDIM * HCDIM];
__device__ __nv_bfloat16 g_w3lo[HCDIM * HCDIM];
__device__ float g_as[N_NODES * NHEADS];
__device__ float g_ad[N_NODES * NHEADS];
__device__ float g_C [N_NODES * NHEADS];          // softmax constant: m + log(s+eps)
__device__ float g_alpha[(size_t)E_TOT * NHEADS]; // raw e (LeakyReLU'd logits)
__device__ int   g_src_sorted[E_TOT];
__device__ int   g_rowptr[N_NODES + 1];
__device__ int   g_cursor[N_NODES];
__device__ int   g_counts[N_NODES];
__device__ int   g_part[64];
__device__ int   g_is64;

// ---------------- PTX helpers (portable: sm_80-era features only) ----------------
__device__ __forceinline__ uint32_t smem_u32(const void* p) {
    uint32_t a;
    asm("{ .reg .u64 t; cvta.to.shared.u64 t, %1; cvt.u32.u64 %0, t; }" : "=r"(a) : "l"(p));
    return a;
}
static __device__ __forceinline__ void cp_async16(uint32_t dst, const void* src, int sz) {
    asm volatile("cp.async.cg.shared.global [%0], [%1], 16, %2;\n"
                 :: "r"(dst), "l"(src), "r"(sz) : "memory");
}
static __device__ __forceinline__ void cp_commit() {
    asm volatile("cp.async.commit_group;" ::: "memory");
}
static __device__ __forceinline__ void cp_wait0() {
    asm volatile("cp.async.wait_group 0;" ::: "memory");
}
static __device__ __forceinline__ void cp_wait1() {
    asm volatile("cp.async.wait_group 1;" ::: "memory");
}

#define LDSM_X4(r, addr) \
    asm volatile("ldmatrix.sync.aligned.m8n8.x4.shared.b16 {%0,%1,%2,%3}, [%4];" \
        : "=r"((r)[0]), "=r"((r)[1]), "=r"((r)[2]), "=r"((r)[3]) : "r"(addr))
#define LDSM_X4_TRANS(r, addr) \
    asm volatile("ldmatrix.sync.aligned.m8n8.x4.trans.shared.b16 {%0,%1,%2,%3}, [%4];" \
        : "=r"((r)[0]), "=r"((r)[1]), "=r"((r)[2]), "=r"((r)[3]) : "r"(addr))
#define MMA_BF16(c, a, b) \
    asm volatile("mma.sync.aligned.m16n8k16.row.col.f32.bf16.bf16.f32 " \
        "{%0,%1,%2,%3},{%4,%5,%6,%7},{%8,%9},{%0,%1,%2,%3};" \
        : "+f"((c)[0]), "+f"((c)[1]), "+f"((c)[2]), "+f"((c)[3]) \
        : "r"((a)[0]), "r"((a)[1]), "r"((a)[2]), "r"((a)[3]), "r"((b)[0]), "r"((b)[1]))

// ---------------- edge dtype handling ----------------
__device__ __forceinline__ int edge_at(const int* p, int idx) {
    return g_is64 ? p[2 * idx] : p[idx];
}

// ---------------- CSR build (5 kernels) ----------------
__global__ void init_detect_kernel(const int* __restrict__ p) {
    int i = blockIdx.x * blockDim.x + threadIdx.x;
    if (i < N_NODES) g_counts[i] = 1;
    if (blockIdx.x == 0) {
        __shared__ int red[256];
        int acc = 0;
        for (int k = threadIdx.x; k < 8192; k += 256) acc |= p[2 * k + 1];
        red[threadIdx.x] = acc;
        __syncthreads();
        for (int s = 128; s > 0; s >>= 1) {
            if (threadIdx.x < s) red[threadIdx.x] |= red[threadIdx.x + s];
            __syncthreads();
        }
        if (threadIdx.x == 0) g_is64 = (red[0] == 0) ? 1 : 0;
    }
}
__global__ void count_kernel(const int* __restrict__ ei) {
    int i = blockIdx.x * blockDim.x + threadIdx.x;
    if (i < NE) atomicAdd(&g_counts[edge_at(ei, NE + i)], 1);
}
__global__ void __launch_bounds__(1024) scan_block_kernel() {
    __shared__ int sm[1024];
    int i = blockIdx.x * 1024 + threadIdx.x;
    int v = (i < N_NODES) ? g_counts[i] : 0;
    sm[threadIdx.x] = v;
    __syncthreads();
    for (int off = 1; off < 1024; off <<= 1) {
        int t = (threadIdx.x >= off) ? sm[threadIdx.x - off] : 0;
        __syncthreads();
        sm[threadIdx.x] += t;
        __syncthreads();
    }
    if (i < N_NODES) g_rowptr[i] = sm[threadIdx.x] - v;   // local exclusive
    if (threadIdx.x == 1023) g_part[blockIdx.x] = sm[1023];  // raw block totals
}
__global__ void __launch_bounds__(1024) scan_add_kernel() {
    __shared__ int base_s;
    if (threadIdx.x == 0) {
        int run = 0;
        for (int b = 0; b < (int)blockIdx.x; b++) run += g_part[b];
        base_s = run;
    }
    __syncthreads();
    int i = blockIdx.x * 1024 + threadIdx.x;
    if (i < N_NODES) {
        int v = g_rowptr[i] + base_s;
        g_rowptr[i] = v;
        g_cursor[i] = v;
    }
    if (i == 0) g_rowptr[N_NODES] = E_TOT;
}
__global__ void fill_kernel(const int* __restrict__ ei) {
    int i = blockIdx.x * blockDim.x + threadIdx.x;
    if (i >= E_TOT) return;
    int src, dst;
    if (i < NE) { src = edge_at(ei, i); dst = edge_at(ei, NE + i); }
    else        { src = dst = i - NE; }
    int pos = atomicAdd(&g_cursor[dst], 1);
    g_src_sorted[pos] = src;
}

// ---------------- small-K GEMM (layer 1, K=18) with fused alpha epilogue ----------------
#define BM 128
#define BN 64
#define BK 16

__global__ void __launch_bounds__(256) gemm_small_kernel(const float* __restrict__ A,
                                                         const float* __restrict__ B,
                                                         const float* __restrict__ a_src,
                                                         const float* __restrict__ a_dst,
                                                         __half* __restrict__ C,
                                                         int M, int K, int Nc) {
    __shared__ float As[BK][BM + 4];
    __shared__ float Bs[BK][BN + 4];
    int tid = threadIdx.x;
    int bn0 = blockIdx.x * BN;
    int bm0 = blockIdx.y * BM;
    int tr = tid >> 4;
    int tc = tid & 15;
    int a_row = tid >> 1;
    int a_cb  = (tid & 1) * 8;
    int b_row = tid >> 4;
    int b_col = (tid & 15) * 4;

    float acc[8][4];
#pragma unroll
    for (int i = 0; i < 8; i++)
#pragma unroll
        for (int j = 0; j < 4; j++) acc[i][j] = 0.f;

    for (int k0 = 0; k0 < K; k0 += BK) {
        int gm = bm0 + a_row;
#pragma unroll
        for (int i = 0; i < 8; i++) {
            int gk = k0 + a_cb + i;
            As[a_cb + i][a_row] = (gm < M && gk < K) ? A[(long long)gm * K + gk] : 0.f;
        }
        {
            int gk = k0 + b_row;
            float4 bv = make_float4(0.f, 0.f, 0.f, 0.f);
            if (gk < K) bv = *(const float4*)&B[(long long)gk * Nc + bn0 + b_col];
            *(float4*)&Bs[b_row][b_col] = bv;
        }
        __syncthreads();
#pragma unroll
        for (int kk = 0; kk < BK; kk++) {
            float a[8], b[4];
#pragma unroll
            for (int i = 0; i < 8; i++) a[i] = As[kk][tr * 8 + i];
#pragma unroll
            for (int j = 0; j < 4; j++) b[j] = Bs[kk][tc * 4 + j];
#pragma unroll
            for (int i = 0; i < 8; i++)
#pragma unroll
                for (int j = 0; j < 4; j++) acc[i][j] += a[i] * b[j];
        }
        __syncthreads();
    }
#pragma unroll
    for (int i = 0; i < 8; i++) {
        int gm = bm0 + tr * 8 + i;
        if (gm < M) {
            __half2 h01 = __floats2half2_rn(acc[i][0], acc[i][1]);
            __half2 h23 = __floats2half2_rn(acc[i][2], acc[i][3]);
            uint2 u;
            u.x = *(uint32_t*)&h01;
            u.y = *(uint32_t*)&h23;
            *(uint2*)&C[(size_t)gm * Nc + bn0 + tc * 4] = u;
        }
    }

    // fused alpha for this head
    {
        int hh = blockIdx.x;
        float pas[8], pad_[8];
#pragma unroll
        for (int i = 0; i < 8; i++) { pas[i] = 0.f; pad_[i] = 0.f; }
#pragma unroll
        for (int j = 0; j < 4; j++) {
            float sj = __ldg(&a_src[hh * CDIM + tc * 4 + j]);
            float dj = __ldg(&a_dst[hh * CDIM + tc * 4 + j]);
#pragma unroll
            for (int i = 0; i < 8; i++) {
                pas[i]  = fmaf(acc[i][j], sj, pas[i]);
                pad_[i] = fmaf(acc[i][j], dj, pad_[i]);
            }
        }
#pragma unroll
        for (int off = 1; off < 16; off <<= 1) {
#pragma unroll
            for (int i = 0; i < 8; i++) {
                pas[i]  += __shfl_xor_sync(0xffffffffu, pas[i], off);
                pad_[i] += __shfl_xor_sync(0xffffffffu, pad_[i], off);
            }
        }
        if (tc == 0) {
#pragma unroll
            for (int i = 0; i < 8; i++) {
                int gm = bm0 + tr * 8 + i;
                if (gm < M) {
                    g_as[gm * NHEADS + hh] = pas[i];
                    g_ad[gm * NHEADS + hh] = pad_[i];
                }
            }
        }
    }
}

// ---------------- W bf16 split ----------------
__global__ void __launch_bounds__(256) wsplit_kernel(const float* __restrict__ W,
                                                     __nv_bfloat16* __restrict__ whi,
                                                     __nv_bfloat16* __restrict__ wlo) {
    int i = blockIdx.x * blockDim.x + threadIdx.x;
    if (i < HCDIM * HCDIM) {
        float v = W[i];
        __nv_bfloat16 hi = __float2bfloat16_rn(v);
        whi[i] = hi;
        wlo[i] = __float2bfloat16_rn(v - __bfloat162float(hi));
    }
}

// ---------------- mma.sync bf16-split GEMM + fused alpha epilogue ----------------
#define KTILES  (HCDIM / 32)      // 16
#define APITCH  80
#define BPITCH  272
#define A_TB    (128 * APITCH)
#define B_TB    (32 * BPITCH)
#define BUF_B   (2 * A_TB + 2 * B_TB)
#define GSMEM   (2 * BUF_B)

__global__ void __launch_bounds__(256, 2)
mma_gemm_kernel(const __nv_bfloat16* __restrict__ Ahi,
                const __nv_bfloat16* __restrict__ Alo,
                const __nv_bfloat16* __restrict__ Whi,
                const __nv_bfloat16* __restrict__ Wlo,
                const float* __restrict__ a_src,
                const float* __restrict__ a_dst,
                __half* __restrict__ C, int M) {
    extern __shared__ char smem[];
    uint32_t sb = smem_u32(smem);
    int tid = threadIdx.x, lane = tid & 31, wid = tid >> 5;
    int wm = wid & 3, wn = wid >> 2;
    int bm0 = blockIdx.y * 128, bn0 = blockIdx.x * 128;

    float acc[2][8][4];
#pragma unroll
    for (int im = 0; im < 2; im++)
#pragma unroll
        for (int in_ = 0; in_ < 8; in_++)
#pragma unroll
            for (int q = 0; q < 4; q++) acc[im][in_][q] = 0.f;

    auto load_tile = [&](int kt, int b) {
        uint32_t base = sb + (uint32_t)b * BUF_B;
#pragma unroll
        for (int m = 0; m < 2; m++) {
            const __nv_bfloat16* srcm = m ? Alo : Ahi;
            uint32_t tb = base + (uint32_t)m * A_TB;
#pragma unroll
            for (int q = 0; q < 2; q++) {
                int idx = q * 256 + tid;
                int r = idx >> 2, ch = idx & 3;
                int gr = bm0 + r;
                int sz = 16;
                if (gr >= M) { gr = 0; sz = 0; }
                cp_async16(tb + (uint32_t)(r * APITCH + ch * 16),
                           srcm + (size_t)gr * HCDIM + kt * 32 + ch * 8, sz);
            }
        }
#pragma unroll
        for (int m = 0; m < 2; m++) {
            const __nv_bfloat16* srcm = m ? Wlo : Whi;
            uint32_t tb = base + 2 * A_TB + (uint32_t)m * B_TB;
#pragma unroll
            for (int q = 0; q < 2; q++) {
                int idx = q * 256 + tid;
                int r = idx >> 4, ch = idx & 15;
                cp_async16(tb + (uint32_t)(r * BPITCH + ch * 16),
                           srcm + (size_t)(kt * 32 + r) * HCDIM + bn0 + ch * 8, 16);
            }
        }
        cp_commit();
    };

    load_tile(0, 0);

    for (int t = 0; t < KTILES; t++) {
        int b = t & 1;
        if (t + 1 < KTILES) { load_tile(t + 1, b ^ 1); cp_wait1(); }
        else cp_wait0();
        __syncthreads();

        uint32_t abase = sb + (uint32_t)b * BUF_B;
        uint32_t bbase = abase + 2 * A_TB;
#pragma unroll
        for (int ks = 0; ks < 2; ks++) {
            uint32_t ah[2][4], al[2][4];
#pragma unroll
            for (int im = 0; im < 2; im++) {
                uint32_t ra = abase
                    + (uint32_t)((wm * 32 + im * 16 + (lane & 15)) * APITCH
                                 + (ks * 16 + (lane >> 4) * 8) * 2);
                LDSM_X4(ah[im], ra);
                LDSM_X4(al[im], ra + A_TB);
            }
            int g = lane >> 3;
#pragma unroll
            for (int in2 = 0; in2 < 4; in2++) {
                uint32_t rb = bbase
                    + (uint32_t)((ks * 16 + (lane & 7) + (g & 1) * 8) * BPITCH
                                 + (wn * 64 + in2 * 16 + (g >> 1) * 8) * 2);
                uint32_t bh[4], bl[4];
                LDSM_X4_TRANS(bh, rb);
                LDSM_X4_TRANS(bl, rb + B_TB);
#pragma unroll
                for (int im = 0; im < 2; im++) {
                    MMA_BF16(acc[im][in2 * 2],     ah[im], (bh + 0));
                    MMA_BF16(acc[im][in2 * 2],     ah[im], (bl + 0));
                    MMA_BF16(acc[im][in2 * 2],     al[im], (bh + 0));
                    MMA_BF16(acc[im][in2 * 2 + 1], ah[im], (bh + 2));
                    MMA_BF16(acc[im][in2 * 2 + 1], ah[im], (bl + 2));
                    MMA_BF16(acc[im][in2 * 2 + 1], al[im], (bh + 2));
                }
            }
        }
        __syncthreads();
    }

    // ---- C store (fp16) ----
#pragma unroll
    for (int im = 0; im < 2; im++) {
        int r0 = bm0 + wm * 32 + im * 16 + (lane >> 2);
#pragma unroll
        for (int in_ = 0; in_ < 8; in_++) {
            int col = bn0 + wn * 64 + in_ * 8 + (lane & 3) * 2;
            if (r0 < M) {
                __half2 hp = __floats2half2_rn(acc[im][in_][0], acc[im][in_][1]);
                *(uint32_t*)&C[(size_t)r0 * HCDIM + col] = *(uint32_t*)&hp;
            }
            if (r0 + 8 < M) {
                __half2 hp = __floats2half2_rn(acc[im][in_][2], acc[im][in_][3]);
                *(uint32_t*)&C[(size_t)(r0 + 8) * HCDIM + col] = *(uint32_t*)&hp;
            }
        }
    }

    // ---- fused alpha: warp's 64 cols = one head ----
    {
        int hh = (bn0 >> 6) + wn;
        float pas[4] = {0.f, 0.f, 0.f, 0.f};
        float pad_[4] = {0.f, 0.f, 0.f, 0.f};
#pragma unroll
        for (int in_ = 0; in_ < 8; in_++) {
            int c0 = in_ * 8 + (lane & 3) * 2;
            float s0 = __ldg(&a_src[hh * CDIM + c0]);
            float s1 = __ldg(&a_src[hh * CDIM + c0 + 1]);
            float d0 = __ldg(&a_dst[hh * CDIM + c0]);
            float d1 = __ldg(&a_dst[hh * CDIM + c0 + 1]);
#pragma unroll
            for (int im = 0; im < 2; im++) {
                pas[im * 2]     += acc[im][in_][0] * s0 + acc[im][in_][1] * s1;
                pas[im * 2 + 1] += acc[im][in_][2] * s0 + acc[im][in_][3] * s1;
                pad_[im * 2]     += acc[im][in_][0] * d0 + acc[im][in_][1] * d1;
                pad_[im * 2 + 1] += acc[im][in_][2] * d0 + acc[im][in_][3] * d1;
            }
        }
#pragma unroll
        for (int k = 0; k < 4; k++) {
            pas[k]  += __shfl_xor_sync(0xffffffffu, pas[k], 1);
            pas[k]  += __shfl_xor_sync(0xffffffffu, pas[k], 2);
            pad_[k] += __shfl_xor_sync(0xffffffffu, pad_[k], 1);
            pad_[k] += __shfl_xor_sync(0xffffffffu, pad_[k], 2);
        }
        if ((lane & 3) == 0) {
#pragma unroll
            for (int im = 0; im < 2; im++) {
                int r0 = bm0 + wm * 32 + im * 16 + (lane >> 2);
                if (r0 < M) {
                    g_as[r0 * NHEADS + hh] = pas[im * 2];
                    g_ad[r0 * NHEADS + hh] = pad_[im * 2];
                }
                if (r0 + 8 < M) {
                    g_as[(r0 + 8) * NHEADS + hh] = pas[im * 2 + 1];
                    g_ad[(r0 + 8) * NHEADS + hh] = pad_[im * 2 + 1];
                }
            }
        }
    }
}

// ---------------- segment softmax: warp per node, 4 edges x 8 heads per iter ----------------
__global__ void stats_kernel() {
    int lane = threadIdx.x & 31;
    int n = (blockIdx.x * blockDim.x + threadIdx.x) >> 5;
    int hh = lane & 7, sub = lane >> 3;
    if (n >= N_NODES) return;
    int row = g_rowptr[n], end = g_rowptr[n + 1];
    float ad = g_ad[n * NHEADS + hh];
    float m = -1e30f, s = 0.f;
    for (int j = row + sub; j < end; j += 4) {
        int src = g_src_sorted[j];
        float e = g_as[src * NHEADS + hh] + ad;
        e = (e > 0.f) ? e : NEG_SLOPE * e;
        g_alpha[(size_t)j * NHEADS + hh] = e;
        float nm = fmaxf(m, e);
        s = s * __expf(m - nm) + __expf(e - nm);
        m = nm;
    }
#pragma unroll
    for (int off = 8; off <= 16; off <<= 1) {
        float mo = __shfl_xor_sync(0xffffffffu, m, off);
        float so = __shfl_xor_sync(0xffffffffu, s, off);
        float nm = fmaxf(m, mo);
        s = s * __expf(m - nm) + so * __expf(mo - nm);
        m = nm;
    }
    if (sub == 0) g_C[n * NHEADS + hh] = m + __logf(s + 1e-16f);
}

// ---------------- heavy aggregation (fp16 h, alpha inline; mode 1 fuses projection) -----
__device__ __forceinline__ uint32_t pack_bf2(float a, float b) {
    __nv_bfloat162 t;
    t.x = __float2bfloat16_rn(a);
    t.y = __float2bfloat16_rn(b);
    return *(uint32_t*)&t;
}

__global__ void __launch_bounds__(128) aggregate_kernel(const __half* __restrict__ hin,
                                                        const float* __restrict__ bias,
                                                        __nv_bfloat16* __restrict__ xhi,
                                                        __nv_bfloat16* __restrict__ xlo,
                                                        const float* __restrict__ Wout,
                                                        const float* __restrict__ bout,
                                                        float* __restrict__ outp,
                                                        int mode) {
    __shared__ float4 sm4[HCDIM / 4];
    __shared__ float x3row[CDIM];
    int n = blockIdx.x;
    int tid = threadIdx.x;
    int head = tid >> 4;
    int row = g_rowptr[n], end = g_rowptr[n + 1];
    float Cc = __ldg(&g_C[n * NHEADS + head]);
    const uint2* h2 = (const uint2*)hin;
    float4 acc = make_float4(0.f, 0.f, 0.f, 0.f);
    int j = row;
    for (; j + 3 < end; j += 4) {
        int s0 = __ldg(&g_src_sorted[j]);
        int s1 = __ldg(&g_src_sorted[j + 1]);
        int s2 = __ldg(&g_src_sorted[j + 2]);
        int s3 = __ldg(&g_src_sorted[j + 3]);
        float a0 = __expf(__ldg(&g_alpha[(size_t)j * NHEADS + head]) - Cc);
        float a1 = __expf(__ldg(&g_alpha[(size_t)(j + 1) * NHEADS + head]) - Cc);
        float a2 = __expf(__ldg(&g_alpha[(size_t)(j + 2) * NHEADS + head]) - Cc);
        float a3 = __expf(__ldg(&g_alpha[(size_t)(j + 3) * NHEADS + head]) - Cc);
        uint2 u0 = __ldg(&h2[(size_t)s0 * (HCDIM / 4) + tid]);
        uint2 u1 = __ldg(&h2[(size_t)s1 * (HCDIM / 4) + tid]);
        uint2 u2 = __ldg(&h2[(size_t)s2 * (HCDIM / 4) + tid]);
        uint2 u3 = __ldg(&h2[(size_t)s3 * (HCDIM / 4) + tid]);
        float2 f0a = __half22float2(*(__half2*)&u0.x), f0b = __half22float2(*(__half2*)&u0.y);
        float2 f1a = __half22float2(*(__half2*)&u1.x), f1b = __half22float2(*(__half2*)&u1.y);
        float2 f2a = __half22float2(*(__half2*)&u2.x), f2b = __half22float2(*(__half2*)&u2.y);
        float2 f3a = __half22float2(*(__half2*)&u3.x), f3b = __half22float2(*(__half2*)&u3.y);
        acc.x = fmaf(a0, f0a.x, fmaf(a1, f1a.x, fmaf(a2, f2a.x, fmaf(a3, f3a.x, acc.x))));
        acc.y = fmaf(a0, f0a.y, fmaf(a1, f1a.y, fmaf(a2, f2a.y, fmaf(a3, f3a.y, acc.y))));
        acc.z = fmaf(a0, f0b.x, fmaf(a1, f1b.x, fmaf(a2, f2b.x, fmaf(a3, f3b.x, acc.z))));
        acc.w = fmaf(a0, f0b.y, fmaf(a1, f1b.y, fmaf(a2, f2b.y, fmaf(a3, f3b.y, acc.w))));
    }
    for (; j < end; j++) {
        int s0 = __ldg(&g_src_sorted[j]);
        float a0 = __expf(__ldg(&g_alpha[(size_t)j * NHEADS + head]) - Cc);
        uint2 u0 = __ldg(&h2[(size_t)s0 * (HCDIM / 4) + tid]);
        float2 f0a = __half22float2(*(__half2*)&u0.x);
        float2 f0b = __half22float2(*(__half2*)&u0.y);
        acc.x = fmaf(a0, f0a.x, acc.x);
        acc.y = fmaf(a0, f0a.y, acc.y);
        acc.z = fmaf(a0, f0b.x, acc.z);
        acc.w = fmaf(a0, f0b.y, acc.w);
    }
    if (mode == 0) {
        float4 b4 = ((const float4*)bias)[tid];
        float vx = acc.x + b4.x; vx = (vx > 0.f) ? vx : expm1f(vx);
        float vy = acc.y + b4.y; vy = (vy > 0.f) ? vy : expm1f(vy);
        float vz = acc.z + b4.z; vz = (vz > 0.f) ? vz : expm1f(vz);
        float vw = acc.w + b4.w; vw = (vw > 0.f) ? vw : expm1f(vw);
        __nv_bfloat16 hx = __float2bfloat16_rn(vx), hy = __float2bfloat16_rn(vy);
        __nv_bfloat16 hz = __float2bfloat16_rn(vz), hw = __float2bfloat16_rn(vw);
        float lx = vx - __bfloat162float(hx), ly = vy - __bfloat162float(hy);
        float lz = vz - __bfloat162float(hz), lw = vw - __bfloat162float(hw);
        size_t base = ((size_t)n * HCDIM + tid * 4) >> 1;
        uint32_t* hip = (uint32_t*)xhi;
        uint32_t* lop = (uint32_t*)xlo;
        __nv_bfloat162 h01; h01.x = hx; h01.y = hy;
        __nv_bfloat162 h23; h23.x = hz; h23.y = hw;
        hip[base]     = *(uint32_t*)&h01;
        hip[base + 1] = *(uint32_t*)&h23;
        lop[base]     = pack_bf2(lx, ly);
        lop[base + 1] = pack_bf2(lz, lw);
    } else {
        sm4[tid] = acc;
        __syncthreads();
        if (tid < 16) {
            float4 s = make_float4(0.f, 0.f, 0.f, 0.f);
#pragma unroll
            for (int hh = 0; hh < NHEADS; hh++) {
                float4 f = sm4[hh * 16 + tid];
                s.x += f.x; s.y += f.y; s.z += f.z; s.w += f.w;
            }
            float4 b4 = ((const float4*)bias)[tid];
            x3row[tid * 4 + 0] = s.x * (1.0f / NHEADS) + b4.x;
            x3row[tid * 4 + 1] = s.y * (1.0f / NHEADS) + b4.y;
            x3row[tid * 4 + 2] = s.z * (1.0f / NHEADS) + b4.z;
            x3row[tid * 4 + 3] = s.w * (1.0f / NHEADS) + b4.w;
        }
        __syncthreads();
        // fused projection: 16 groups of 8 threads; group o computes out[n][o] (o<15)
        int o = tid >> 3, c8 = tid & 7;
        float accp = 0.f;
        if (o < OUT_DIM) {
#pragma unroll
            for (int c = 0; c < 8; c++) {
                int cc = c8 * 8 + c;
                accp = fmaf(x3row[cc], __ldg(&Wout[cc * OUT_DIM + o]), accp);
            }
        }
        accp += __shfl_xor_sync(0xffffffffu, accp, 1);
        accp += __shfl_xor_sync(0xffffffffu, accp, 2);
        accp += __shfl_xor_sync(0xffffffffu, accp, 4);
        if (c8 == 0 && o < OUT_DIM)
            outp[(size_t)n * OUT_DIM + o] = accp + __ldg(&bout[o]);
    }
}

// ---------------- launch ----------------
extern "C" void kernel_launch(void* const* d_in, const int* in_sizes, int n_in,
                              void* d_out, int out_size) {
    const float* x    = (const float*)d_in[0];
    const int*   ei   = (const int*)d_in[1];
    const float* W1   = (const float*)d_in[2];
    const float* a1s  = (const float*)d_in[3];
    const float* a1d  = (const float*)d_in[4];
    const float* b1   = (const float*)d_in[5];
    const float* W2   = (const float*)d_in[6];
    const float* a2s  = (const float*)d_in[7];
    const float* a2d  = (const float*)d_in[8];
    const float* b2   = (const float*)d_in[9];
    const float* W3   = (const float*)d_in[10];
    const float* a3s  = (const float*)d_in[11];
    const float* a3d  = (const float*)d_in[12];
    const float* b3   = (const float*)d_in[13];
    const float* Wout = (const float*)d_in[14];
    const float* bout = (const float*)d_in[15];
    float* out = (float*)d_out;

    __half *p_h;
    __nv_bfloat16 *p_xhi, *p_xlo, *p_w2hi, *p_w2lo, *p_w3hi, *p_w3lo;
    cudaGetSymbolAddress((void**)&p_h,    g_h);
    cudaGetSymbolAddress((void**)&p_xhi,  g_xhi);
    cudaGetSymbolAddress((void**)&p_xlo,  g_xlo);
    cudaGetSymbolAddress((void**)&p_w2hi, g_w2hi);
    cudaGetSymbolAddress((void**)&p_w2lo, g_w2lo);
    cudaGetSymbolAddress((void**)&p_w3hi, g_w3hi);
    cudaGetSymbolAddress((void**)&p_w3lo, g_w3lo);

    cudaFuncSetAttribute(mma_gemm_kernel, cudaFuncAttributeMaxDynamicSharedMemorySize, GSMEM);

    const int scan_blocks = (N_NODES + 1023) / 1024;

    init_detect_kernel<<<(N_NODES + 255) / 256, 256>>>(ei);
    count_kernel<<<(NE + 255) / 256, 256>>>(ei);
    scan_block_kernel<<<scan_blocks, 1024>>>();
    scan_add_kernel<<<scan_blocks, 1024>>>();
    fill_kernel<<<(E_TOT + 255) / 256, 256>>>(ei);

    int wsplit_blocks = (HCDIM * HCDIM + 255) / 256;
    wsplit_kernel<<<wsplit_blocks, 256>>>(W2, p_w2hi, p_w2lo);
    wsplit_kernel<<<wsplit_blocks, 256>>>(W3, p_w3hi, p_w3lo);

    dim3 sgrid(HCDIM / BN, (N_NODES + BM - 1) / BM);
    dim3 mgrid(HCDIM / 128, (N_NODES + 127) / 128);
    int stats_blocks = (N_NODES * 32 + 255) / 256;   // warp per node

    // ---- layer 1 ----
    gemm_small_kernel<<<sgrid, 256>>>(x, W1, a1s, a1d, p_h, N_NODES, F_IN, HCDIM);
    stats_kernel<<<stats_blocks, 256>>>();
    aggregate_kernel<<<N_NODES, 128>>>(p_h, b1, p_xhi, p_xlo, nullptr, nullptr, nullptr, 0);

    // ---- layer 2 ----
    mma_gemm_kernel<<<mgrid, 256, GSMEM>>>(p_xhi, p_xlo, p_w2hi, p_w2lo, a2s, a2d, p_h, N_NODES);
    stats_kernel<<<stats_blocks, 256>>>();
    aggregate_kernel<<<N_NODES, 128>>>(p_h, b2, p_xhi, p_xlo, nullptr, nullptr, nullptr, 0);

    // ---- layer 3 (aggregate + mean + bias + output projection fused) ----
    mma_gemm_kernel<<<mgrid, 256, GSMEM>>>(p_xhi, p_xlo, p_w3hi, p_w3lo, a3s, a3d, p_h, N_NODES);
    stats_kernel<<<stats_blocks, 256>>>();
    aggregate_kernel<<<N_NODES, 128>>>(p_h, b3, nullptr, nullptr, Wout, bout, out, 1);
}